// round 6
// baseline (speedup 1.0000x reference)
#include <cuda_runtime.h>
#include <math.h>

#define NSIG 65536
#define NAT  512
#define MDIM 64
#define NBLK 2048            // NSIG / 32 signals per block
#define SMEM_FLOATS (2048 + 8192 + 2112)
#define SMEM_BYTES  (SMEM_FLOATS * 4)

// ---------------- device globals (scratch; no allocations allowed) ----------
__device__ __align__(16) float  g_dnormJ[MDIM][NAT];   // [m][j]
__device__ __align__(16) float  g_dnormT[NAT][MDIM];   // [j][m]
__device__ __align__(16) float  g_G[NAT][NAT];         // Gram (raw then scaled)
__device__ float  g_rn[NAT];
__device__ double g_partial[NBLK];
__device__ unsigned g_done = 0;

// ---------------- f32x2 packed-FMA helpers (Blackwell) ----------------------
__device__ __forceinline__ unsigned long long fma2(unsigned long long a,
                                                   unsigned long long b,
                                                   unsigned long long c) {
    unsigned long long r;
    asm("fma.rn.f32x2 %0, %1, %2, %3;" : "=l"(r) : "l"(a), "l"(b), "l"(c));
    return r;
}
__device__ __forceinline__ unsigned long long pack2(float x) {
    unsigned long long r;
    asm("mov.b64 %0, {%1, %1};" : "=l"(r) : "f"(x));
    return r;
}
__device__ __forceinline__ float2 unpack2(unsigned long long v) {
    float2 f;
    asm("mov.b64 {%0, %1}, %2;" : "=f"(f.x), "=f"(f.y) : "l"(v));
    return f;
}

// ---------------- KA: raw Gram  Ghat = D^T D --------------------------------
__global__ void k_gramraw(const float* __restrict__ dict) {
    __shared__ float di[MDIM];
    const int i = blockIdx.x, tid = threadIdx.x;
    if (tid < MDIM) di[tid] = __ldg(dict + tid * NAT + i);
    __syncthreads();
    for (int j = tid; j < NAT; j += 128) {
        float s0 = 0.f, s1 = 0.f, s2 = 0.f, s3 = 0.f;
        #pragma unroll
        for (int m = 0; m < MDIM; m += 4) {
            s0 += di[m + 0] * __ldg(dict + (m + 0) * NAT + j);
            s1 += di[m + 1] * __ldg(dict + (m + 1) * NAT + j);
            s2 += di[m + 2] * __ldg(dict + (m + 2) * NAT + j);
            s3 += di[m + 3] * __ldg(dict + (m + 3) * NAT + j);
        }
        g_G[i][j] = (s0 + s1) + (s2 + s3);
    }
}

// ---------------- KB: rn_j = 1 / max(sqrt(Ghat[j][j]), eps) -----------------
__global__ void k_rn() {
    int j = blockIdx.x * 256 + threadIdx.x;
    if (j < NAT)
        g_rn[j] = 1.f / fmaxf(sqrtf(g_G[j][j]), 1e-10f);
}

// ---------------- KC: normalized dictionary ---------------------------------
__global__ void k_dnorm(const float* __restrict__ dict) {
    int idx = blockIdx.x * 256 + threadIdx.x;     // 32768 total
    int m = idx >> 9, j = idx & 511;
    float d = __ldg(dict + idx) * g_rn[j];
    g_dnormJ[m][j] = d;
    g_dnormT[j][m] = d;
}

// ---------------- KD: scale Gram in place  G = Ghat * rn_i * rn_j -----------
__global__ void k_gscale() {
    int idx = blockIdx.x * 256 + threadIdx.x;     // 262144 total
    int i = idx >> 9, j = idx & 511;
    float* gl = &g_G[0][0];
    gl[idx] = gl[idx] * (g_rn[i] * g_rn[j]);
}

// atom index owned by (lane, t):  j = 128*(t>>2) + 4*lane + (t&3)
#define JMAP(lane, t) (128 * ((t) >> 2) + 4 * (lane) + ((t) & 3))

// ---------------- K3: fused zero + GEMM + per-warp OMP + outputs + loss -----
__global__ void __launch_bounds__(256, 3)
k_main(const float* __restrict__ ze, float* __restrict__ out_z,
       float* __restrict__ out_coef, float* __restrict__ out_loss) {
    extern __shared__ float smem[];
    float* sh_x = smem;                    // [64][32]       2048
    float* sh_h = smem + 2048;             // [32][256] tp   8192
    float* sh_z = smem + 2048 + 8192;      // [64][33] pad   2112
    __shared__ double sh_red[256];
    __shared__ int sh_last;

    const int tid  = threadIdx.x;
    const int lane = tid & 31;
    const int wid  = tid >> 5;
    const int tile = blockIdx.x * 32;
    const int b    = tile >> 10;
    const int hw0  = tile & 1023;
    const float* zb = ze + (size_t)b * 65536 + hw0;

    // ---- zero this block's 32 coeff columns (hides under GEMM) ----
    {
        float* cz = out_coef + tile;
        for (int i = tid; i < NAT * 32; i += 256) {
            int j = i >> 5, sl = i & 31;
            cz[(size_t)j * 65536 + sl] = 0.f;
        }
    }

    // ---- load X tile: sh_x[m][sl] (coalesced) ----
    for (int i = tid; i < 2048; i += 256) {
        int m = i >> 5, sl = i & 31;
        sh_x[i] = zb[m * 1024 + sl];
    }
    __syncthreads();

    // ================== two passes: GEMM(2 sigs) then OMP(2 sigs) ==========
    #pragma unroll 1
    for (int pass = 0; pass < 2; pass++) {
        // ---- GEMM: h[sig][j] for sigs wid*4 + 2*pass + {0,1} (f32x2) ----
        {
            unsigned long long acc[2][8];
            #pragma unroll
            for (int c = 0; c < 2; c++)
                #pragma unroll
                for (int p = 0; p < 8; p++) acc[c][p] = 0ull;

            for (int m = 0; m < MDIM; m++) {
                const ulonglong2* drow = (const ulonglong2*)(&g_dnormJ[m][0]);
                ulonglong2 d0 = drow[lane];
                ulonglong2 d1 = drow[32 + lane];
                ulonglong2 d2 = drow[64 + lane];
                ulonglong2 d3 = drow[96 + lane];
                unsigned long long dv[8] = {d0.x, d0.y, d1.x, d1.y,
                                            d2.x, d2.y, d3.x, d3.y};
                float2 xs2 = *(const float2*)(sh_x + m * 32 + wid * 4 + 2 * pass);
                float xc[2] = {xs2.x, xs2.y};
                #pragma unroll
                for (int c = 0; c < 2; c++) {
                    unsigned long long xp = pack2(xc[c]);
                    #pragma unroll
                    for (int p = 0; p < 8; p++)
                        acc[c][p] = fma2(dv[p], xp, acc[c][p]);
                }
            }
            // stage to thread-private smem (kills acc live range; no sync needed)
            #pragma unroll
            for (int c = 0; c < 2; c++)
                #pragma unroll
                for (int p = 0; p < 8; p++) {
                    float2 f = unpack2(acc[c][p]);
                    sh_h[(c * 16 + 2 * p + 0) * 256 + tid] = f.x;
                    sh_h[(c * 16 + 2 * p + 1) * 256 + tid] = f.y;
                }
        }

        // ---- OMP for the two staged signals ----
        #pragma unroll 1
        for (int sc2 = 0; sc2 < 2; ++sc2) {
            const int sl = wid * 4 + 2 * pass + sc2;
            const int s  = tile + sl;

            float h[16];
            #pragma unroll
            for (int t = 0; t < 16; t++) h[t] = sh_h[(sc2 * 16 + t) * 256 + tid];

            unsigned mask16 = 0u;
            int   idxs[5];
            float xs[5], xsold[5], y[5], rinv[5];
            float Lm[5][5];               // only off-diagonal entries used
            #pragma unroll
            for (int i = 0; i < 5; i++) xsold[i] = 0.f;

            #pragma unroll
            for (int k = 0; k < 5; k++) {
                // ---- local abs-argmax: balanced tree, depth 4 ----
                float a[16]; int mt[16];  // meta = (t<<1)|sign
                #pragma unroll
                for (int t = 0; t < 16; t++) {
                    unsigned hb = __float_as_uint(h[t]);
                    a[t]  = ((mask16 >> t) & 1u) ? -1.f
                                                 : __uint_as_float(hb & 0x7FFFFFFFu);
                    mt[t] = (t << 1) | (int)(hb >> 31);
                }
                float v8[8]; int m8[8];
                #pragma unroll
                for (int p = 0; p < 8; p++) {
                    bool r = a[2*p+1] > a[2*p];
                    v8[p] = r ? a[2*p+1] : a[2*p];
                    m8[p] = r ? mt[2*p+1] : mt[2*p];
                }
                float v4[4]; int m4[4];
                #pragma unroll
                for (int p = 0; p < 4; p++) {
                    bool r = v8[2*p+1] > v8[2*p];
                    v4[p] = r ? v8[2*p+1] : v8[2*p];
                    m4[p] = r ? m8[2*p+1] : m8[2*p];
                }
                float v2[2]; int m2[2];
                #pragma unroll
                for (int p = 0; p < 2; p++) {
                    bool r = v4[2*p+1] > v4[2*p];
                    v2[p] = r ? v4[2*p+1] : v4[2*p];
                    m2[p] = r ? m4[2*p+1] : m4[2*p];
                }
                bool r1 = v2[1] > v2[0];
                float lv = r1 ? v2[1] : v2[0];
                int   lm = r1 ? m2[1] : m2[0];
                int   lt = lm >> 1;
                unsigned labs = __float_as_uint(lv);
                unsigned lj   = (unsigned)JMAP(lane, lt);
                unsigned lsgn = (unsigned)(lm & 1);

                // ---- cross-lane argmax via redux (first-index tie-break) ----
                unsigned wmax = __reduce_max_sync(0xffffffffu, labs);
                unsigned cand = (labs == wmax) ? ((lj << 1) | lsgn) : 0xFFFFFFFFu;
                unsigned kmin = __reduce_min_sync(0xffffffffu, cand);
                int   bestj = (int)(kmin >> 1);
                float absv  = __uint_as_float(wmax);
                float h_sel = (kmin & 1u) ? -absv : absv;
                if (((bestj >> 2) & 31) == lane) {
                    int tb = (((bestj >> 7) << 2) | (bestj & 3));
                    mask16 |= 1u << tb;
                }
                idxs[k] = bestj;

                // ---- G_stack scalars via symmetry + reconstruct hbar[bestj] --
                float gs[4];
                #pragma unroll
                for (int i = 0; i < 4; i++) if (i < k)
                    gs[i] = __ldg(&g_G[bestj][idxs[i]]);
                float hbk = h_sel;
                #pragma unroll
                for (int i = 0; i < 4; i++) if (i < k) hbk += xs[i] * gs[i];

                // ---- incremental Cholesky (diag kept only as rinv) ----
                if (k == 0) {
                    rinv[0] = 1.f;
                } else {
                    float w[4]; float s2 = 0.f;
                    #pragma unroll
                    for (int i = 0; i < 4; i++) if (i < k) {
                        float v = gs[i];
                        #pragma unroll
                        for (int j2 = 0; j2 < 4; j2++)
                            if (j2 < i) v -= Lm[i][j2] * w[j2];
                        w[i] = v * rinv[i];
                        Lm[k][i] = w[i];
                        s2 += w[i] * w[i];
                    }
                    rinv[k] = __frcp_rn(sqrtf(1.f - s2));
                }

                // ---- incremental forward solve (y[0..k-1] unchanged) ----
                {
                    float v = hbk;
                    #pragma unroll
                    for (int j2 = 0; j2 < 4; j2++)
                        if (j2 < k) v -= Lm[k][j2] * y[j2];
                    y[k] = v * rinv[k];
                }
                // ---- backward solve (size k+1) ----
                #pragma unroll
                for (int i = 4; i >= 0; i--) if (i <= k) {
                    float v = y[i];
                    #pragma unroll
                    for (int j2 = 0; j2 < 5; j2++)
                        if (j2 > i && j2 <= k) v -= Lm[j2][i] * xs[j2];
                    xs[i] = v * rinv[i];
                }

                // ---- delta residual update: h -= sum_i dx[i]*G[idxs[i]][:] --
                if (k < 4) {
                    float dx[4];
                    #pragma unroll
                    for (int i = 0; i < 4; i++) if (i <= k) {
                        dx[i] = xs[i] - xsold[i];
                        xsold[i] = xs[i];
                    }
                    #pragma unroll
                    for (int i = 0; i < 4; i++) if (i <= k) {
                        const float4* gri = (const float4*)(&g_G[idxs[i]][0]);
                        #pragma unroll
                        for (int q = 0; q < 4; q++) {
                            float4 g4 = __ldg(gri + 32 * q + lane);
                            h[4*q+0] -= dx[i] * g4.x;
                            h[4*q+1] -= dx[i] * g4.y;
                            h[4*q+2] -= dx[i] * g4.z;
                            h[4*q+3] -= dx[i] * g4.w;
                        }
                    }
                }
            }

            // ---- coeffs scatter (lane i writes atom i) ----
            #pragma unroll
            for (int i = 0; i < 5; i++)
                if (lane == i) out_coef[(size_t)idxs[i] * 65536 + s] = xs[i];

            // ---- sparse reconstruction, staged for coalesced write ----
            float r0 = 0.f, r1 = 0.f;
            #pragma unroll
            for (int i = 0; i < 5; i++) {
                const float* dr = &g_dnormT[idxs[i]][0];
                r0 += xs[i] * dr[lane];
                r1 += xs[i] * dr[lane + 32];
            }
            sh_z[lane * 33 + sl]        = r0;
            sh_z[(lane + 32) * 33 + sl] = r1;
        }
    }
    __syncthreads();

    // ---- Phase 3: coalesced z_dl_st write + deterministic loss reduce ----
    double part = 0.0;
    float* oz = out_z + (size_t)b * 65536 + hw0;
    for (int i = tid; i < 2048; i += 256) {
        int m = i >> 5, sl = i & 31;
        float xv = sh_x[m * 32 + sl];
        float r  = sh_z[m * 33 + sl];
        float dd = r - xv;
        part += (double)dd * (double)dd;
        oz[m * 1024 + sl] = xv + dd;   // z_e + (z_dl - z_e)
    }
    sh_red[tid] = part;
    __syncthreads();
    for (int sft = 128; sft; sft >>= 1) {
        if (tid < sft) sh_red[tid] += sh_red[tid + sft];
        __syncthreads();
    }

    // ---- fused final loss: last block reduces g_partial deterministically --
    if (tid == 0) {
        g_partial[blockIdx.x] = sh_red[0];
        __threadfence();
        unsigned ticket = atomicAdd(&g_done, 1u);
        sh_last = (ticket == NBLK - 1);
    }
    __syncthreads();
    if (sh_last) {
        double p = 0.0;
        for (int i = tid; i < NBLK; i += 256) p += g_partial[i];
        sh_red[tid] = p;
        __syncthreads();
        for (int sft = 128; sft; sft >>= 1) {
            if (tid < sft) sh_red[tid] += sh_red[tid + sft];
            __syncthreads();
        }
        if (tid == 0) {
            out_loss[0] = (float)(1.25 * sh_red[0] / 4194304.0);
            atomicExch(&g_done, 0u);   // reset for next graph replay
        }
    }
}

// ---------------- launch ------------------------------------------------------
extern "C" void kernel_launch(void* const* d_in, const int* in_sizes, int n_in,
                              void* d_out, int out_size) {
    const float* ze   = (const float*)d_in[0];
    const float* dict = (const float*)d_in[1];
    float* out      = (float*)d_out;
    float* out_z    = out;                 // 4,194,304
    float* out_loss = out + 4194304;       // 1
    float* out_coef = out + 4194305;       // 33,554,432

    cudaFuncSetAttribute(k_main, cudaFuncAttributeMaxDynamicSharedMemorySize,
                         SMEM_BYTES);

    k_gramraw<<<NAT, 128>>>(dict);
    k_rn<<<2, 256>>>();
    k_dnorm<<<128, 256>>>(dict);
    k_gscale<<<1024, 256>>>();
    k_main<<<NBLK, 256, SMEM_BYTES>>>(ze, out_z, out_coef, out_loss);
}

// round 7
// speedup vs baseline: 1.0493x; 1.0493x over previous
#include <cuda_runtime.h>
#include <math.h>

#define NSIG 65536
#define NAT  512
#define MDIM 64
#define NBLK 2048            // NSIG / 32 signals per block
#define SMEM_FLOATS (2048 + 16384 + 2112)
#define SMEM_BYTES  (SMEM_FLOATS * 4)

// ---------------- device globals (scratch; no allocations allowed) ----------
__device__ __align__(16) float  g_dnormJ[MDIM][NAT];   // [m][j]
__device__ __align__(16) float  g_dnormT[NAT][MDIM];   // [j][m]
__device__ __align__(16) float  g_G[NAT][NAT];         // Gram (raw then scaled)
__device__ float  g_rn[NAT];
__device__ double g_partial[NBLK];
__device__ unsigned g_done = 0;

// ---------------- f32x2 packed-FMA helpers (Blackwell) ----------------------
__device__ __forceinline__ unsigned long long fma2(unsigned long long a,
                                                   unsigned long long b,
                                                   unsigned long long c) {
    unsigned long long r;
    asm("fma.rn.f32x2 %0, %1, %2, %3;" : "=l"(r) : "l"(a), "l"(b), "l"(c));
    return r;
}
__device__ __forceinline__ unsigned long long pack2(float x) {
    unsigned long long r;
    asm("mov.b64 %0, {%1, %1};" : "=l"(r) : "f"(x));
    return r;
}
__device__ __forceinline__ float2 unpack2(unsigned long long v) {
    float2 f;
    asm("mov.b64 {%0, %1}, %2;" : "=f"(f.x), "=f"(f.y) : "l"(v));
    return f;
}

// ---------------- KA: raw Gram  Ghat = D^T D --------------------------------
__global__ void k_gramraw(const float* __restrict__ dict) {
    __shared__ float di[MDIM];
    const int i = blockIdx.x, tid = threadIdx.x;
    if (tid < MDIM) di[tid] = __ldg(dict + tid * NAT + i);
    __syncthreads();
    for (int j = tid; j < NAT; j += 128) {
        float s0 = 0.f, s1 = 0.f, s2 = 0.f, s3 = 0.f;
        #pragma unroll
        for (int m = 0; m < MDIM; m += 4) {
            s0 += di[m + 0] * __ldg(dict + (m + 0) * NAT + j);
            s1 += di[m + 1] * __ldg(dict + (m + 1) * NAT + j);
            s2 += di[m + 2] * __ldg(dict + (m + 2) * NAT + j);
            s3 += di[m + 3] * __ldg(dict + (m + 3) * NAT + j);
        }
        g_G[i][j] = (s0 + s1) + (s2 + s3);
    }
}

// ---------------- KB: rn_j = 1 / max(sqrt(Ghat[j][j]), eps) -----------------
__global__ void k_rn() {
    int j = blockIdx.x * 256 + threadIdx.x;
    if (j < NAT)
        g_rn[j] = 1.f / fmaxf(sqrtf(g_G[j][j]), 1e-10f);
}

// ---------------- KC: normalized dictionary ---------------------------------
__global__ void k_dnorm(const float* __restrict__ dict) {
    int idx = blockIdx.x * 256 + threadIdx.x;     // 32768 total
    int m = idx >> 9, j = idx & 511;
    float d = __ldg(dict + idx) * g_rn[j];
    g_dnormJ[m][j] = d;
    g_dnormT[j][m] = d;
}

// ---------------- KD: scale Gram in place  G = Ghat * rn_i * rn_j -----------
__global__ void k_gscale() {
    int idx = blockIdx.x * 256 + threadIdx.x;     // 262144 total
    int i = idx >> 9, j = idx & 511;
    float* gl = &g_G[0][0];
    gl[idx] = gl[idx] * (g_rn[i] * g_rn[j]);
}

// atom index owned by (lane, t):  j = 128*(t>>2) + 4*lane + (t&3)
// (ascending t <=> ascending j within a lane: tie-break by t == tie-break by j)
#define JMAP(lane, t) (128 * ((t) >> 2) + 4 * (lane) + ((t) & 3))
#define TRI(i, j) ((i) * ((i) - 1) / 2 + (j))    // lower-tri flat index, i > j

// ---------------- K3: fused zero + GEMM + dual-chain OMP + outputs + loss ---
__global__ void __launch_bounds__(256, 2)
k_main(const float* __restrict__ ze, float* __restrict__ out_z,
       float* __restrict__ out_coef, float* __restrict__ out_loss) {
    extern __shared__ float smem[];
    float* sh_x = smem;                    // [64][32]        2048
    float* sh_h = smem + 2048;             // [64][256] tp    16384
    float* sh_z = smem + 2048 + 16384;     // [64][33] pad    2112
    __shared__ double sh_red[256];
    __shared__ int sh_last;

    const int tid  = threadIdx.x;
    const int lane = tid & 31;
    const int wid  = tid >> 5;
    const int tile = blockIdx.x * 32;
    const int b    = tile >> 10;
    const int hw0  = tile & 1023;
    const float* zb = ze + (size_t)b * 65536 + hw0;

    // ---- zero this block's 32 coeff columns (hides under GEMM) ----
    {
        float* cz = out_coef + tile;
        for (int i = tid; i < NAT * 32; i += 256) {
            int j = i >> 5, sl = i & 31;
            cz[(size_t)j * 65536 + sl] = 0.f;
        }
    }

    // ---- load X tile: sh_x[m][sl] (coalesced) ----
    for (int i = tid; i < 2048; i += 256) {
        int m = i >> 5, sl = i & 31;
        sh_x[i] = zb[m * 1024 + sl];
    }
    __syncthreads();

    // ---- Phase 1: single-pass GEMM, 4 signals; stage to thread-private smem
    {
        unsigned long long acc[4][8];
        #pragma unroll
        for (int c = 0; c < 4; c++)
            #pragma unroll
            for (int p = 0; p < 8; p++) acc[c][p] = 0ull;

        for (int m = 0; m < MDIM; m++) {
            const ulonglong2* drow = (const ulonglong2*)(&g_dnormJ[m][0]);
            ulonglong2 d0 = drow[lane];
            ulonglong2 d1 = drow[32 + lane];
            ulonglong2 d2 = drow[64 + lane];
            ulonglong2 d3 = drow[96 + lane];
            unsigned long long dv[8] = {d0.x, d0.y, d1.x, d1.y,
                                        d2.x, d2.y, d3.x, d3.y};
            float4 xs4 = *(const float4*)(sh_x + m * 32 + wid * 4);
            float xc[4] = {xs4.x, xs4.y, xs4.z, xs4.w};
            #pragma unroll
            for (int c = 0; c < 4; c++) {
                unsigned long long xp = pack2(xc[c]);
                #pragma unroll
                for (int p = 0; p < 8; p++)
                    acc[c][p] = fma2(dv[p], xp, acc[c][p]);
            }
        }
        #pragma unroll
        for (int c = 0; c < 4; c++)
            #pragma unroll
            for (int p = 0; p < 8; p++) {
                float2 f = unpack2(acc[c][p]);
                sh_h[(c * 16 + 2 * p + 0) * 256 + tid] = f.x;
                sh_h[(c * 16 + 2 * p + 1) * 256 + tid] = f.y;
            }
    }
    // thread-private staging: no __syncthreads needed

    // ---- Phase 2: OMP, TWO interleaved chains per warp per pass ----
    #pragma unroll 1
    for (int sp = 0; sp < 2; ++sp) {
        // chains c=0,1 -> signals sl = wid*4 + 2*sp + c
        float h[2][16];
        #pragma unroll
        for (int c = 0; c < 2; c++)
            #pragma unroll
            for (int t = 0; t < 16; t++)
                h[c][t] = sh_h[((2 * sp + c) * 16 + t) * 256 + tid];

        unsigned mask[2] = {0u, 0u};
        int   idxs[2][5];
        float xs[2][5], y[2][5], rv[2][5], Lm[2][10];

        #pragma unroll
        for (int k = 0; k < 5; k++) {
            // ---- local abs-argmax trees (both chains, independent) ----
            unsigned labs[2], lj[2], lsgn[2];
            #pragma unroll
            for (int c = 0; c < 2; c++) {
                float v8[8]; int m8[8];
                #pragma unroll
                for (int p = 0; p < 8; p++) {
                    unsigned hb0 = __float_as_uint(h[c][2*p]);
                    unsigned hb1 = __float_as_uint(h[c][2*p+1]);
                    float a0 = ((mask[c] >> (2*p)) & 1u) ? -1.f
                             : __uint_as_float(hb0 & 0x7FFFFFFFu);
                    float a1 = ((mask[c] >> (2*p+1)) & 1u) ? -1.f
                             : __uint_as_float(hb1 & 0x7FFFFFFFu);
                    bool r = a1 > a0;
                    v8[p] = r ? a1 : a0;
                    m8[p] = r ? (((2*p+1) << 1) | (int)(hb1 >> 31))
                              : (((2*p)   << 1) | (int)(hb0 >> 31));
                }
                float v4[4]; int m4[4];
                #pragma unroll
                for (int p = 0; p < 4; p++) {
                    bool r = v8[2*p+1] > v8[2*p];
                    v4[p] = r ? v8[2*p+1] : v8[2*p];
                    m4[p] = r ? m8[2*p+1] : m8[2*p];
                }
                float v2[2]; int m2[2];
                #pragma unroll
                for (int p = 0; p < 2; p++) {
                    bool r = v4[2*p+1] > v4[2*p];
                    v2[p] = r ? v4[2*p+1] : v4[2*p];
                    m2[p] = r ? m4[2*p+1] : m4[2*p];
                }
                bool r1 = v2[1] > v2[0];
                float lv = r1 ? v2[1] : v2[0];
                int   lm = r1 ? m2[1] : m2[0];
                labs[c] = __float_as_uint(lv);
                lj[c]   = (unsigned)JMAP(lane, lm >> 1);
                lsgn[c] = (unsigned)(lm & 1);
            }

            // ---- cross-lane argmax: redux pairs back-to-back (overlap) ----
            unsigned wmax[2], kmin[2];
            #pragma unroll
            for (int c = 0; c < 2; c++)
                wmax[c] = __reduce_max_sync(0xffffffffu, labs[c]);
            #pragma unroll
            for (int c = 0; c < 2; c++) {
                unsigned cand = (labs[c] == wmax[c])
                              ? ((lj[c] << 1) | lsgn[c]) : 0xFFFFFFFFu;
                kmin[c] = __reduce_min_sync(0xffffffffu, cand);
            }

            int bestj[2]; float h_sel[2];
            #pragma unroll
            for (int c = 0; c < 2; c++) {
                bestj[c] = (int)(kmin[c] >> 1);
                float av = __uint_as_float(wmax[c]);
                h_sel[c] = (kmin[c] & 1u) ? -av : av;
                if (((bestj[c] >> 2) & 31) == lane) {
                    int tb = (((bestj[c] >> 7) << 2) | (bestj[c] & 3));
                    mask[c] |= 1u << tb;
                }
                idxs[c][k] = bestj[c];
            }

            // ---- G_stack scalars (both chains issued together) ----
            float gs[2][4];
            #pragma unroll
            for (int c = 0; c < 2; c++)
                #pragma unroll
                for (int i = 0; i < 4; i++) if (i < k)
                    gs[c][i] = __ldg(&g_G[bestj[c]][idxs[c][i]]);

            #pragma unroll
            for (int c = 0; c < 2; c++) {
                // ---- reconstruct hbar[bestj] ----
                float hbk = h_sel[c];
                #pragma unroll
                for (int i = 0; i < 4; i++) if (i < k) hbk += xs[c][i] * gs[c][i];

                // ---- incremental Cholesky ----
                if (k == 0) {
                    rv[c][0] = 1.f;
                } else {
                    float w[4]; float s2 = 0.f;
                    #pragma unroll
                    for (int i = 0; i < 4; i++) if (i < k) {
                        float v = gs[c][i];
                        #pragma unroll
                        for (int j2 = 0; j2 < 4; j2++)
                            if (j2 < i) v -= Lm[c][TRI(i, j2)] * w[j2];
                        w[i] = v * rv[c][i];
                        Lm[c][TRI(k, i)] = w[i];
                        s2 += w[i] * w[i];
                    }
                    rv[c][k] = __frcp_rn(sqrtf(1.f - s2));
                }

                // ---- incremental forward solve ----
                {
                    float v = hbk;
                    #pragma unroll
                    for (int j2 = 0; j2 < 4; j2++)
                        if (j2 < k) v -= Lm[c][TRI(k, j2)] * y[c][j2];
                    y[c][k] = v * rv[c][k];
                }
            }

            // ---- backward solves with in-place dx (both chains) ----
            float dx[2][5];
            #pragma unroll
            for (int c = 0; c < 2; c++) {
                #pragma unroll
                for (int i = 4; i >= 0; i--) if (i <= k) {
                    float v = y[c][i];
                    #pragma unroll
                    for (int j2 = 0; j2 < 5; j2++)
                        if (j2 > i && j2 <= k) v -= Lm[c][TRI(j2, i)] * xs[c][j2];
                    float xn = v * rv[c][i];
                    dx[c][i] = (i < k) ? (xn - xs[c][i]) : xn;
                    xs[c][i] = xn;
                }
            }

            // ---- delta residual updates (loads for both chains overlap) ----
            if (k < 4) {
                #pragma unroll
                for (int c = 0; c < 2; c++) {
                    #pragma unroll
                    for (int i = 0; i < 4; i++) if (i <= k) {
                        const float4* gri = (const float4*)(&g_G[idxs[c][i]][0]);
                        #pragma unroll
                        for (int q = 0; q < 4; q++) {
                            float4 g4 = __ldg(gri + 32 * q + lane);
                            h[c][4*q+0] -= dx[c][i] * g4.x;
                            h[c][4*q+1] -= dx[c][i] * g4.y;
                            h[c][4*q+2] -= dx[c][i] * g4.z;
                            h[c][4*q+3] -= dx[c][i] * g4.w;
                        }
                    }
                }
            }
        }

        // ---- outputs for both chains ----
        #pragma unroll
        for (int c = 0; c < 2; c++) {
            const int sl = wid * 4 + 2 * sp + c;
            const int s  = tile + sl;
            #pragma unroll
            for (int i = 0; i < 5; i++)
                if (lane == i) out_coef[(size_t)idxs[c][i] * 65536 + s] = xs[c][i];

            float r0 = 0.f, r1 = 0.f;
            #pragma unroll
            for (int i = 0; i < 5; i++) {
                const float* dr = &g_dnormT[idxs[c][i]][0];
                r0 += xs[c][i] * dr[lane];
                r1 += xs[c][i] * dr[lane + 32];
            }
            sh_z[lane * 33 + sl]        = r0;
            sh_z[(lane + 32) * 33 + sl] = r1;
        }
    }
    __syncthreads();

    // ---- Phase 3: coalesced z_dl_st write + deterministic loss reduce ----
    double part = 0.0;
    float* oz = out_z + (size_t)b * 65536 + hw0;
    for (int i = tid; i < 2048; i += 256) {
        int m = i >> 5, sl = i & 31;
        float xv = sh_x[m * 32 + sl];
        float r  = sh_z[m * 33 + sl];
        float dd = r - xv;
        part += (double)dd * (double)dd;
        oz[m * 1024 + sl] = xv + dd;   // z_e + (z_dl - z_e)
    }
    sh_red[tid] = part;
    __syncthreads();
    for (int sft = 128; sft; sft >>= 1) {
        if (tid < sft) sh_red[tid] += sh_red[tid + sft];
        __syncthreads();
    }

    // ---- fused final loss: last block reduces g_partial deterministically --
    if (tid == 0) {
        g_partial[blockIdx.x] = sh_red[0];
        __threadfence();
        unsigned ticket = atomicAdd(&g_done, 1u);
        sh_last = (ticket == NBLK - 1);
    }
    __syncthreads();
    if (sh_last) {
        double p = 0.0;
        for (int i = tid; i < NBLK; i += 256) p += g_partial[i];
        sh_red[tid] = p;
        __syncthreads();
        for (int sft = 128; sft; sft >>= 1) {
            if (tid < sft) sh_red[tid] += sh_red[tid + sft];
            __syncthreads();
        }
        if (tid == 0) {
            out_loss[0] = (float)(1.25 * sh_red[0] / 4194304.0);
            atomicExch(&g_done, 0u);   // reset for next graph replay
        }
    }
}

// ---------------- launch ------------------------------------------------------
extern "C" void kernel_launch(void* const* d_in, const int* in_sizes, int n_in,
                              void* d_out, int out_size) {
    const float* ze   = (const float*)d_in[0];
    const float* dict = (const float*)d_in[1];
    float* out      = (float*)d_out;
    float* out_z    = out;                 // 4,194,304
    float* out_loss = out + 4194304;       // 1
    float* out_coef = out + 4194305;       // 33,554,432

    cudaFuncSetAttribute(k_main, cudaFuncAttributeMaxDynamicSharedMemorySize,
                         SMEM_BYTES);

    k_gramraw<<<NAT, 128>>>(dict);
    k_rn<<<2, 256>>>();
    k_dnorm<<<128, 256>>>(dict);
    k_gscale<<<1024, 256>>>();
    k_main<<<NBLK, 256, SMEM_BYTES>>>(ze, out_z, out_coef, out_loss);
}

// round 8
// speedup vs baseline: 1.0571x; 1.0074x over previous
#include <cuda_runtime.h>
#include <math.h>

#define NSIG 65536
#define NAT  512
#define MDIM 64
#define NBLK 2048            // NSIG / 32 signals per block
#define SMEM_FLOATS (2048 + 16384 + 2112)
#define SMEM_BYTES  (SMEM_FLOATS * 4)

// ---------------- device globals (scratch; no allocations allowed) ----------
__device__ __align__(16) float  g_dnormJ[MDIM][NAT];   // [m][j]
__device__ __align__(16) float  g_dnormT[NAT][MDIM];   // [j][m]
__device__ __align__(16) float  g_G[NAT][NAT];         // Gram (raw then scaled)
__device__ float  g_rn[NAT];
__device__ double g_partial[NBLK];
__device__ unsigned g_done = 0;

// ---------------- f32x2 packed-FMA helpers (Blackwell) ----------------------
__device__ __forceinline__ unsigned long long fma2(unsigned long long a,
                                                   unsigned long long b,
                                                   unsigned long long c) {
    unsigned long long r;
    asm("fma.rn.f32x2 %0, %1, %2, %3;" : "=l"(r) : "l"(a), "l"(b), "l"(c));
    return r;
}
__device__ __forceinline__ unsigned long long pack2(float x) {
    unsigned long long r;
    asm("mov.b64 %0, {%1, %1};" : "=l"(r) : "f"(x));
    return r;
}
__device__ __forceinline__ float2 unpack2(unsigned long long v) {
    float2 f;
    asm("mov.b64 {%0, %1}, %2;" : "=f"(f.x), "=f"(f.y) : "l"(v));
    return f;
}

// ---------------- KA: raw Gram  Ghat = D^T D --------------------------------
__global__ void k_gramraw(const float* __restrict__ dict) {
    __shared__ float di[MDIM];
    const int i = blockIdx.x, tid = threadIdx.x;
    if (tid < MDIM) di[tid] = __ldg(dict + tid * NAT + i);
    __syncthreads();
    for (int j = tid; j < NAT; j += 128) {
        float s0 = 0.f, s1 = 0.f, s2 = 0.f, s3 = 0.f;
        #pragma unroll
        for (int m = 0; m < MDIM; m += 4) {
            s0 += di[m + 0] * __ldg(dict + (m + 0) * NAT + j);
            s1 += di[m + 1] * __ldg(dict + (m + 1) * NAT + j);
            s2 += di[m + 2] * __ldg(dict + (m + 2) * NAT + j);
            s3 += di[m + 3] * __ldg(dict + (m + 3) * NAT + j);
        }
        g_G[i][j] = (s0 + s1) + (s2 + s3);
    }
}

// ---------------- KB: rn_j = 1 / max(sqrt(Ghat[j][j]), eps) -----------------
__global__ void k_rn() {
    int j = blockIdx.x * 256 + threadIdx.x;
    if (j < NAT)
        g_rn[j] = 1.f / fmaxf(sqrtf(g_G[j][j]), 1e-10f);
}

// ---------------- KC: fused dnorm + Gram scaling (one launch) ---------------
__global__ void k_prep(const float* __restrict__ dict) {
    int bid = blockIdx.x;
    if (bid < 128) {                               // normalized dictionary
        int idx = bid * 256 + threadIdx.x;         // 32768 total
        int m = idx >> 9, j = idx & 511;
        float d = __ldg(dict + idx) * g_rn[j];
        g_dnormJ[m][j] = d;
        g_dnormT[j][m] = d;
    } else {                                       // G = Ghat * rn_i * rn_j
        int idx = (bid - 128) * 256 + threadIdx.x; // 262144 total
        int i = idx >> 9, j = idx & 511;
        float* gl = &g_G[0][0];
        gl[idx] = gl[idx] * (g_rn[i] * g_rn[j]);
    }
}

// atom index owned by (lane, t):  j = 128*(t>>2) + 4*lane + (t&3)
// (ascending t <=> ascending j within a lane: tie-break by t == tie-break by j)
#define JMAP(lane, t) (128 * ((t) >> 2) + 4 * (lane) + ((t) & 3))
#define TRI(i, j) ((i) * ((i) - 1) / 2 + (j))    // lower-tri flat index, i > j

// local masked abs-argmax over 16 owned atoms (balanced tree, depth 4)
#define LOCAL_ARGMAX(hc, mk, LABS, LJ, LSGN) do {                            \
    float v8[8]; int m8[8];                                                  \
    _Pragma("unroll")                                                        \
    for (int p = 0; p < 8; p++) {                                            \
        unsigned hb0 = __float_as_uint((hc)[2*p]);                           \
        unsigned hb1 = __float_as_uint((hc)[2*p+1]);                         \
        float a0 = (((mk) >> (2*p)) & 1u) ? 0.f                              \
                 : __uint_as_float(hb0 & 0x7FFFFFFFu);                       \
        float a1 = (((mk) >> (2*p+1)) & 1u) ? 0.f                            \
                 : __uint_as_float(hb1 & 0x7FFFFFFFu);                       \
        bool r = a1 > a0;                                                    \
        v8[p] = r ? a1 : a0;                                                 \
        m8[p] = r ? (((2*p+1) << 1) | (int)(hb1 >> 31))                      \
                  : (((2*p)   << 1) | (int)(hb0 >> 31));                     \
    }                                                                        \
    float v4[4]; int m4[4];                                                  \
    _Pragma("unroll")                                                        \
    for (int p = 0; p < 4; p++) {                                            \
        bool r = v4##_guard(v8[2*p+1] > v8[2*p]);                            \
        v4[p] = r ? v8[2*p+1] : v8[2*p];                                     \
        m4[p] = r ? m8[2*p+1] : m8[2*p];                                     \
    }                                                                        \
    float v2[2]; int m2[2];                                                  \
    _Pragma("unroll")                                                        \
    for (int p = 0; p < 2; p++) {                                            \
        bool r = v4[2*p+1] > v4[2*p];                                        \
        v2[p] = r ? v4[2*p+1] : v4[2*p];                                     \
        m2[p] = r ? m4[2*p+1] : m4[2*p];                                     \
    }                                                                        \
    bool r1 = v2[1] > v2[0];                                                 \
    float lv = r1 ? v2[1] : v2[0];                                           \
    int   lm = r1 ? m2[1] : m2[0];                                           \
    (LABS) = __float_as_uint(lv);                                            \
    (LJ)   = (unsigned)JMAP(lane, lm >> 1);                                  \
    (LSGN) = (unsigned)(lm & 1);                                             \
} while (0)
#define v4_guard(x) (x)

// ---------------- K3: fused zero + GEMM + dual-chain OMP + outputs + loss ---
__global__ void __launch_bounds__(256, 2)
k_main(const float* __restrict__ ze, float* __restrict__ out_z,
       float* __restrict__ out_coef, float* __restrict__ out_loss) {
    extern __shared__ float smem[];
    float* sh_x = smem;                    // [64][32]        2048
    float* sh_h = smem + 2048;             // [64][256] tp    16384
    float* sh_z = smem + 2048 + 16384;     // [64][33] pad    2112
    __shared__ double sh_red[256];
    __shared__ int sh_last;

    const int tid  = threadIdx.x;
    const int lane = tid & 31;
    const int wid  = tid >> 5;
    const int tile = blockIdx.x * 32;
    const int b    = tile >> 10;
    const int hw0  = tile & 1023;
    const float* zb = ze + (size_t)b * 65536 + hw0;

    // ---- zero this block's 32 coeff columns (hides under GEMM) ----
    {
        float* cz = out_coef + tile;
        for (int i = tid; i < NAT * 32; i += 256) {
            int j = i >> 5, sl = i & 31;
            cz[(size_t)j * 65536 + sl] = 0.f;
        }
    }

    // ---- load X tile: sh_x[m][sl] (coalesced) ----
    for (int i = tid; i < 2048; i += 256) {
        int m = i >> 5, sl = i & 31;
        sh_x[i] = zb[m * 1024 + sl];
    }
    __syncthreads();

    // ---- Phase 1: single-pass GEMM, 4 signals; stage to thread-private smem
    {
        unsigned long long acc[4][8];
        #pragma unroll
        for (int c = 0; c < 4; c++)
            #pragma unroll
            for (int p = 0; p < 8; p++) acc[c][p] = 0ull;

        for (int m = 0; m < MDIM; m++) {
            const ulonglong2* drow = (const ulonglong2*)(&g_dnormJ[m][0]);
            ulonglong2 d0 = drow[lane];
            ulonglong2 d1 = drow[32 + lane];
            ulonglong2 d2 = drow[64 + lane];
            ulonglong2 d3 = drow[96 + lane];
            unsigned long long dv[8] = {d0.x, d0.y, d1.x, d1.y,
                                        d2.x, d2.y, d3.x, d3.y};
            float4 xs4 = *(const float4*)(sh_x + m * 32 + wid * 4);
            float xc[4] = {xs4.x, xs4.y, xs4.z, xs4.w};
            #pragma unroll
            for (int c = 0; c < 4; c++) {
                unsigned long long xp = pack2(xc[c]);
                #pragma unroll
                for (int p = 0; p < 8; p++)
                    acc[c][p] = fma2(dv[p], xp, acc[c][p]);
            }
        }
        #pragma unroll
        for (int c = 0; c < 4; c++)
            #pragma unroll
            for (int p = 0; p < 8; p++) {
                float2 f = unpack2(acc[c][p]);
                sh_h[(c * 16 + 2 * p + 0) * 256 + tid] = f.x;
                sh_h[(c * 16 + 2 * p + 1) * 256 + tid] = f.y;
            }
    }
    // thread-private staging: no __syncthreads needed

    // ---- Phase 2: OMP, TWO interleaved chains per warp per pass ----
    #pragma unroll 1
    for (int sp = 0; sp < 2; ++sp) {
        // chains c=0,1 -> signals sl = wid*4 + 2*sp + c
        float h[2][16];
        #pragma unroll
        for (int c = 0; c < 2; c++)
            #pragma unroll
            for (int t = 0; t < 16; t++)
                h[c][t] = sh_h[((2 * sp + c) * 16 + t) * 256 + tid];

        unsigned mask[2] = {0u, 0u};
        int   idxs[2][5];
        float xs[2][5], y[2][5], rv[2][5], Lm[2][10];
        unsigned labs[2], lj[2], lsgn[2];

        // initial local argmax (fused into the update loop for k>=1)
        #pragma unroll
        for (int c = 0; c < 2; c++)
            LOCAL_ARGMAX(h[c], mask[c], labs[c], lj[c], lsgn[c]);

        #pragma unroll
        for (int k = 0; k < 5; k++) {
            // ---- cross-lane argmax: redux pairs back-to-back (overlap) ----
            unsigned wmax[2], kmin[2];
            #pragma unroll
            for (int c = 0; c < 2; c++)
                wmax[c] = __reduce_max_sync(0xffffffffu, labs[c]);
            #pragma unroll
            for (int c = 0; c < 2; c++) {
                unsigned cand = (labs[c] == wmax[c])
                              ? ((lj[c] << 1) | lsgn[c]) : 0xFFFFFFFFu;
                kmin[c] = __reduce_min_sync(0xffffffffu, cand);
            }

            int bestj[2]; float h_sel[2];
            #pragma unroll
            for (int c = 0; c < 2; c++) {
                bestj[c] = (int)(kmin[c] >> 1);
                float av = __uint_as_float(wmax[c]);
                h_sel[c] = (kmin[c] & 1u) ? -av : av;
                if (((bestj[c] >> 2) & 31) == lane) {
                    int tb = (((bestj[c] >> 7) << 2) | (bestj[c] & 3));
                    mask[c] |= 1u << tb;
                }
                idxs[c][k] = bestj[c];
            }

            // ---- G_stack scalars (both chains issued together) ----
            float gs[2][4];
            #pragma unroll
            for (int c = 0; c < 2; c++)
                #pragma unroll
                for (int i = 0; i < 4; i++) if (i < k)
                    gs[c][i] = __ldg(&g_G[bestj[c]][idxs[c][i]]);

            #pragma unroll
            for (int c = 0; c < 2; c++) {
                // ---- reconstruct hbar[bestj] ----
                float hbk = h_sel[c];
                #pragma unroll
                for (int i = 0; i < 4; i++) if (i < k) hbk += xs[c][i] * gs[c][i];

                // ---- incremental Cholesky ----
                if (k == 0) {
                    rv[c][0] = 1.f;
                } else {
                    float w[4]; float s2 = 0.f;
                    #pragma unroll
                    for (int i = 0; i < 4; i++) if (i < k) {
                        float v = gs[c][i];
                        #pragma unroll
                        for (int j2 = 0; j2 < 4; j2++)
                            if (j2 < i) v -= Lm[c][TRI(i, j2)] * w[j2];
                        w[i] = (i == 0) ? v : v * rv[c][i];
                        Lm[c][TRI(k, i)] = w[i];
                        s2 += w[i] * w[i];
                    }
                    rv[c][k] = __frcp_rn(sqrtf(1.f - s2));
                }

                // ---- incremental forward solve ----
                {
                    float v = hbk;
                    #pragma unroll
                    for (int j2 = 0; j2 < 4; j2++)
                        if (j2 < k) v -= Lm[c][TRI(k, j2)] * y[c][j2];
                    y[c][k] = (k == 0) ? v : v * rv[c][k];
                }
            }

            // ---- backward solves with in-place dx (both chains) ----
            float dx[2][5];
            #pragma unroll
            for (int c = 0; c < 2; c++) {
                #pragma unroll
                for (int i = 4; i >= 0; i--) if (i <= k) {
                    float v = y[c][i];
                    #pragma unroll
                    for (int j2 = 0; j2 < 5; j2++)
                        if (j2 > i && j2 <= k) v -= Lm[c][TRI(j2, i)] * xs[c][j2];
                    float xn = (i == 0) ? v : v * rv[c][i];
                    dx[c][i] = (i < k) ? (xn - xs[c][i]) : xn;
                    xs[c][i] = xn;
                }
            }

            // ---- fused: delta residual update + NEXT local argmax ----
            if (k < 4) {
                #pragma unroll
                for (int c = 0; c < 2; c++) {
                    #pragma unroll
                    for (int i = 0; i < 4; i++) if (i <= k) {
                        const float4* gri = (const float4*)(&g_G[idxs[c][i]][0]);
                        #pragma unroll
                        for (int q = 0; q < 4; q++) {
                            float4 g4 = __ldg(gri + 32 * q + lane);
                            h[c][4*q+0] -= dx[c][i] * g4.x;
                            h[c][4*q+1] -= dx[c][i] * g4.y;
                            h[c][4*q+2] -= dx[c][i] * g4.z;
                            h[c][4*q+3] -= dx[c][i] * g4.w;
                        }
                    }
                }
                // next iteration's local argmax, adjacent to the updates so the
                // SEL/FMNMX tree interleaves with in-flight loads
                #pragma unroll
                for (int c = 0; c < 2; c++)
                    LOCAL_ARGMAX(h[c], mask[c], labs[c], lj[c], lsgn[c]);
            }
        }

        // ---- outputs for both chains ----
        #pragma unroll
        for (int c = 0; c < 2; c++) {
            const int sl = wid * 4 + 2 * sp + c;
            const int s  = tile + sl;
            #pragma unroll
            for (int i = 0; i < 5; i++)
                if (lane == i) out_coef[(size_t)idxs[c][i] * 65536 + s] = xs[c][i];

            float r0 = 0.f, r1 = 0.f;
            #pragma unroll
            for (int i = 0; i < 5; i++) {
                const float* dr = &g_dnormT[idxs[c][i]][0];
                r0 += xs[c][i] * dr[lane];
                r1 += xs[c][i] * dr[lane + 32];
            }
            sh_z[lane * 33 + sl]        = r0;
            sh_z[(lane + 32) * 33 + sl] = r1;
        }
    }
    __syncthreads();

    // ---- Phase 3: coalesced z_dl_st write + deterministic loss reduce ----
    double part = 0.0;
    float* oz = out_z + (size_t)b * 65536 + hw0;
    for (int i = tid; i < 2048; i += 256) {
        int m = i >> 5, sl = i & 31;
        float xv = sh_x[m * 32 + sl];
        float r  = sh_z[m * 33 + sl];
        float dd = r - xv;
        part += (double)dd * (double)dd;
        oz[m * 1024 + sl] = xv + dd;   // z_e + (z_dl - z_e)
    }
    sh_red[tid] = part;
    __syncthreads();
    for (int sft = 128; sft; sft >>= 1) {
        if (tid < sft) sh_red[tid] += sh_red[tid + sft];
        __syncthreads();
    }

    // ---- fused final loss: last block reduces g_partial deterministically --
    if (tid == 0) {
        g_partial[blockIdx.x] = sh_red[0];
        __threadfence();
        unsigned ticket = atomicAdd(&g_done, 1u);
        sh_last = (ticket == NBLK - 1);
    }
    __syncthreads();
    if (sh_last) {
        double p = 0.0;
        for (int i = tid; i < NBLK; i += 256) p += g_partial[i];
        sh_red[tid] = p;
        __syncthreads();
        for (int sft = 128; sft; sft >>= 1) {
            if (tid < sft) sh_red[tid] += sh_red[tid + sft];
            __syncthreads();
        }
        if (tid == 0) {
            out_loss[0] = (float)(1.25 * sh_red[0] / 4194304.0);
            atomicExch(&g_done, 0u);   // reset for next graph replay
        }
    }
}

// ---------------- launch ------------------------------------------------------
extern "C" void kernel_launch(void* const* d_in, const int* in_sizes, int n_in,
                              void* d_out, int out_size) {
    const float* ze   = (const float*)d_in[0];
    const float* dict = (const float*)d_in[1];
    float* out      = (float*)d_out;
    float* out_z    = out;                 // 4,194,304
    float* out_loss = out + 4194304;       // 1
    float* out_coef = out + 4194305;       // 33,554,432

    cudaFuncSetAttribute(k_main, cudaFuncAttributeMaxDynamicSharedMemorySize,
                         SMEM_BYTES);

    k_gramraw<<<NAT, 128>>>(dict);
    k_rn<<<2, 256>>>();
    k_prep<<<1152, 256>>>(dict);
    k_main<<<NBLK, 256, SMEM_BYTES>>>(ze, out_z, out_coef, out_loss);
}

// round 9
// speedup vs baseline: 1.0760x; 1.0179x over previous
#include <cuda_runtime.h>
#include <math.h>

#define NSIG 65536
#define NAT  512
#define MDIM 64
#define NBLK 2048            // NSIG / 32 signals per block
#define SMEM_FLOATS (2048 + 16384 + 2112)
#define SMEM_BYTES  (SMEM_FLOATS * 4)

// ---------------- device globals (scratch; no allocations allowed) ----------
__device__ __align__(16) float  g_dnormJ[MDIM][NAT];   // [m][j]
__device__ __align__(16) float  g_dnormT[NAT][MDIM];   // [j][m]
__device__ __align__(16) float  g_G[NAT][NAT];         // Gram (raw then scaled)
__device__ float  g_rn[NAT];
__device__ double g_partial[NBLK];
__device__ unsigned g_done = 0;

// ---------------- f32x2 packed-FMA helpers (Blackwell) ----------------------
__device__ __forceinline__ unsigned long long fma2(unsigned long long a,
                                                   unsigned long long b,
                                                   unsigned long long c) {
    unsigned long long r;
    asm("fma.rn.f32x2 %0, %1, %2, %3;" : "=l"(r) : "l"(a), "l"(b), "l"(c));
    return r;
}
__device__ __forceinline__ unsigned long long pack2(float x) {
    unsigned long long r;
    asm("mov.b64 %0, {%1, %1};" : "=l"(r) : "f"(x));
    return r;
}
__device__ __forceinline__ float2 unpack2(unsigned long long v) {
    float2 f;
    asm("mov.b64 {%0, %1}, %2;" : "=f"(f.x), "=f"(f.y) : "l"(v));
    return f;
}

// ---------------- KA: raw Gram  Ghat = D^T D  (+ fused rn from diagonal) ----
__global__ void k_gramraw(const float* __restrict__ dict) {
    __shared__ float di[MDIM];
    const int i = blockIdx.x, tid = threadIdx.x;
    if (tid < MDIM) di[tid] = __ldg(dict + tid * NAT + i);
    __syncthreads();
    for (int j = tid; j < NAT; j += 128) {
        float s0 = 0.f, s1 = 0.f, s2 = 0.f, s3 = 0.f;
        #pragma unroll
        for (int m = 0; m < MDIM; m += 4) {
            s0 += di[m + 0] * __ldg(dict + (m + 0) * NAT + j);
            s1 += di[m + 1] * __ldg(dict + (m + 1) * NAT + j);
            s2 += di[m + 2] * __ldg(dict + (m + 2) * NAT + j);
            s3 += di[m + 3] * __ldg(dict + (m + 3) * NAT + j);
        }
        float v = (s0 + s1) + (s2 + s3);
        g_G[i][j] = v;
        if (j == i)                      // block i owns the diagonal element
            g_rn[i] = 1.f / fmaxf(sqrtf(v), 1e-10f);
    }
}

// ---------------- KC: fused dnorm + Gram scaling (one launch) ---------------
__global__ void k_prep(const float* __restrict__ dict) {
    int bid = blockIdx.x;
    if (bid < 128) {                               // normalized dictionary
        int idx = bid * 256 + threadIdx.x;         // 32768 total
        int m = idx >> 9, j = idx & 511;
        float d = __ldg(dict + idx) * g_rn[j];
        g_dnormJ[m][j] = d;
        g_dnormT[j][m] = d;
    } else {                                       // G = Ghat * rn_i * rn_j
        int idx = (bid - 128) * 256 + threadIdx.x; // 262144 total
        int i = idx >> 9, j = idx & 511;
        float* gl = &g_G[0][0];
        gl[idx] = gl[idx] * (g_rn[i] * g_rn[j]);
    }
}

// atom index owned by (lane, t):  j = 128*(t>>2) + 4*lane + (t&3)
// (ascending t <=> ascending j within a lane: tie-break by t == tie-break by j)
#define JMAP(lane, t) (128 * ((t) >> 2) + 4 * (lane) + ((t) & 3))
#define TRI(i, j) ((i) * ((i) - 1) / 2 + (j))    // lower-tri flat index, i > j

// local masked abs-argmax over 16 owned atoms (balanced tree, depth 4)
#define LOCAL_ARGMAX(hc, mk, LABS, LJ, LSGN) do {                            \
    float v8[8]; int m8[8];                                                  \
    _Pragma("unroll")                                                        \
    for (int p = 0; p < 8; p++) {                                            \
        unsigned hb0 = __float_as_uint((hc)[2*p]);                           \
        unsigned hb1 = __float_as_uint((hc)[2*p+1]);                         \
        float a0 = (((mk) >> (2*p)) & 1u) ? 0.f                              \
                 : __uint_as_float(hb0 & 0x7FFFFFFFu);                       \
        float a1 = (((mk) >> (2*p+1)) & 1u) ? 0.f                            \
                 : __uint_as_float(hb1 & 0x7FFFFFFFu);                       \
        bool r = a1 > a0;                                                    \
        v8[p] = r ? a1 : a0;                                                 \
        m8[p] = r ? (((2*p+1) << 1) | (int)(hb1 >> 31))                      \
                  : (((2*p)   << 1) | (int)(hb0 >> 31));                     \
    }                                                                        \
    float v4[4]; int m4[4];                                                  \
    _Pragma("unroll")                                                        \
    for (int p = 0; p < 4; p++) {                                            \
        bool r = v8[2*p+1] > v8[2*p];                                        \
        v4[p] = r ? v8[2*p+1] : v8[2*p];                                     \
        m4[p] = r ? m8[2*p+1] : m8[2*p];                                     \
    }                                                                        \
    float v2[2]; int m2[2];                                                  \
    _Pragma("unroll")                                                        \
    for (int p = 0; p < 2; p++) {                                            \
        bool r = v4[2*p+1] > v4[2*p];                                        \
        v2[p] = r ? v4[2*p+1] : v4[2*p];                                     \
        m2[p] = r ? m4[2*p+1] : m4[2*p];                                     \
    }                                                                        \
    bool r1 = v2[1] > v2[0];                                                 \
    float lv = r1 ? v2[1] : v2[0];                                           \
    int   lm = r1 ? m2[1] : m2[0];                                           \
    (LABS) = __float_as_uint(lv);                                            \
    (LJ)   = (unsigned)JMAP(lane, lm >> 1);                                  \
    (LSGN) = (unsigned)(lm & 1);                                             \
} while (0)

// ---------------- K3: fused zero + GEMM + dual-chain OMP + outputs + loss ---
__global__ void __launch_bounds__(256, 2)
k_main(const float* __restrict__ ze, float* __restrict__ out_z,
       float* __restrict__ out_coef, float* __restrict__ out_loss) {
    extern __shared__ float smem[];
    float* sh_x = smem;                    // [64][32]        2048
    float* sh_h = smem + 2048;             // [64][256] tp    16384
    float* sh_z = smem + 2048 + 16384;     // [64][33] pad    2112
    __shared__ double sh_red[256];
    __shared__ int sh_last;

    const int tid  = threadIdx.x;
    const int lane = tid & 31;
    const int wid  = tid >> 5;
    const int tile = blockIdx.x * 32;
    const int b    = tile >> 10;
    const int hw0  = tile & 1023;
    const float* zb = ze + (size_t)b * 65536 + hw0;

    // ---- zero this block's 32 coeff columns (hides under GEMM) ----
    {
        float* cz = out_coef + tile;
        for (int i = tid; i < NAT * 32; i += 256) {
            int j = i >> 5, sl = i & 31;
            cz[(size_t)j * 65536 + sl] = 0.f;
        }
    }

    // ---- load X tile: sh_x[m][sl] (coalesced) ----
    for (int i = tid; i < 2048; i += 256) {
        int m = i >> 5, sl = i & 31;
        sh_x[i] = zb[m * 1024 + sl];
    }
    __syncthreads();

    // ---- Phase 1: single-pass GEMM, 4 signals; stage to thread-private smem
    {
        unsigned long long acc[4][8];
        #pragma unroll
        for (int c = 0; c < 4; c++)
            #pragma unroll
            for (int p = 0; p < 8; p++) acc[c][p] = 0ull;

        for (int m = 0; m < MDIM; m++) {
            const ulonglong2* drow = (const ulonglong2*)(&g_dnormJ[m][0]);
            ulonglong2 d0 = drow[lane];
            ulonglong2 d1 = drow[32 + lane];
            ulonglong2 d2 = drow[64 + lane];
            ulonglong2 d3 = drow[96 + lane];
            unsigned long long dv[8] = {d0.x, d0.y, d1.x, d1.y,
                                        d2.x, d2.y, d3.x, d3.y};
            float4 xs4 = *(const float4*)(sh_x + m * 32 + wid * 4);
            float xc[4] = {xs4.x, xs4.y, xs4.z, xs4.w};
            #pragma unroll
            for (int c = 0; c < 4; c++) {
                unsigned long long xp = pack2(xc[c]);
                #pragma unroll
                for (int p = 0; p < 8; p++)
                    acc[c][p] = fma2(dv[p], xp, acc[c][p]);
            }
        }
        #pragma unroll
        for (int c = 0; c < 4; c++)
            #pragma unroll
            for (int p = 0; p < 8; p++) {
                float2 f = unpack2(acc[c][p]);
                sh_h[(c * 16 + 2 * p + 0) * 256 + tid] = f.x;
                sh_h[(c * 16 + 2 * p + 1) * 256 + tid] = f.y;
            }
    }
    // thread-private staging: no __syncthreads needed

    // ---- Phase 2: OMP, TWO interleaved chains per warp per pass ----
    #pragma unroll 1
    for (int sp = 0; sp < 2; ++sp) {
        // chains c=0,1 -> signals sl = wid*4 + 2*sp + c
        float h[2][16];
        #pragma unroll
        for (int c = 0; c < 2; c++)
            #pragma unroll
            for (int t = 0; t < 16; t++)
                h[c][t] = sh_h[((2 * sp + c) * 16 + t) * 256 + tid];

        unsigned mask[2] = {0u, 0u};
        int   idxs[2][5];
        float xs[2][5], y[2][5], rv[2][5], Lm[2][10];
        unsigned labs[2], lj[2], lsgn[2];

        // initial local argmax (fused into the update loop for k>=1)
        #pragma unroll
        for (int c = 0; c < 2; c++)
            LOCAL_ARGMAX(h[c], mask[c], labs[c], lj[c], lsgn[c]);

        #pragma unroll
        for (int k = 0; k < 5; k++) {
            // ---- cross-lane argmax: redux pairs back-to-back (overlap) ----
            unsigned wmax[2], kmin[2];
            #pragma unroll
            for (int c = 0; c < 2; c++)
                wmax[c] = __reduce_max_sync(0xffffffffu, labs[c]);
            #pragma unroll
            for (int c = 0; c < 2; c++) {
                unsigned cand = (labs[c] == wmax[c])
                              ? ((lj[c] << 1) | lsgn[c]) : 0xFFFFFFFFu;
                kmin[c] = __reduce_min_sync(0xffffffffu, cand);
            }

            int bestj[2]; float h_sel[2];
            #pragma unroll
            for (int c = 0; c < 2; c++) {
                bestj[c] = (int)(kmin[c] >> 1);
                float av = __uint_as_float(wmax[c]);
                h_sel[c] = (kmin[c] & 1u) ? -av : av;
                if (((bestj[c] >> 2) & 31) == lane) {
                    int tb = (((bestj[c] >> 7) << 2) | (bestj[c] & 3));
                    mask[c] |= 1u << tb;
                }
                idxs[c][k] = bestj[c];
            }

            // ---- G_stack scalars for Cholesky (both chains issued together) --
            float gs[2][4];
            #pragma unroll
            for (int c = 0; c < 2; c++)
                #pragma unroll
                for (int i = 0; i < 4; i++) if (i < k)
                    gs[c][i] = __ldg(&g_G[bestj[c]][idxs[c][i]]);

            #pragma unroll
            for (int c = 0; c < 2; c++) {
                // ---- incremental Cholesky ----
                if (k == 0) {
                    rv[c][0] = 1.f;
                } else {
                    float w[4]; float s2 = 0.f;
                    #pragma unroll
                    for (int i = 0; i < 4; i++) if (i < k) {
                        float v = gs[c][i];
                        #pragma unroll
                        for (int j2 = 0; j2 < 4; j2++)
                            if (j2 < i) v -= Lm[c][TRI(i, j2)] * w[j2];
                        w[i] = (i == 0) ? v : v * rv[c][i];
                        Lm[c][TRI(k, i)] = w[i];
                        s2 += w[i] * w[i];
                    }
                    rv[c][k] = __frcp_rn(sqrtf(1.f - s2));
                }

                // ---- forward solve collapses exactly:  y_k = h_sel * rinv_k
                // (h_sel = hbar[new] - w.y  and row k of L is exactly w)
                y[c][k] = (k == 0) ? h_sel[c] : h_sel[c] * rv[c][k];
            }

            // ---- backward solves with in-place dx (both chains) ----
            float dx[2][5];
            #pragma unroll
            for (int c = 0; c < 2; c++) {
                #pragma unroll
                for (int i = 4; i >= 0; i--) if (i <= k) {
                    float v = y[c][i];
                    #pragma unroll
                    for (int j2 = 0; j2 < 5; j2++)
                        if (j2 > i && j2 <= k) v -= Lm[c][TRI(j2, i)] * xs[c][j2];
                    float xn = (i == 0) ? v : v * rv[c][i];
                    dx[c][i] = (i < k) ? (xn - xs[c][i]) : xn;
                    xs[c][i] = xn;
                }
            }

            // ---- fused: delta residual update + NEXT local argmax ----
            if (k < 4) {
                #pragma unroll
                for (int c = 0; c < 2; c++) {
                    #pragma unroll
                    for (int i = 0; i < 4; i++) if (i <= k) {
                        const float4* gri = (const float4*)(&g_G[idxs[c][i]][0]);
                        #pragma unroll
                        for (int q = 0; q < 4; q++) {
                            float4 g4 = __ldg(gri + 32 * q + lane);
                            h[c][4*q+0] -= dx[c][i] * g4.x;
                            h[c][4*q+1] -= dx[c][i] * g4.y;
                            h[c][4*q+2] -= dx[c][i] * g4.z;
                            h[c][4*q+3] -= dx[c][i] * g4.w;
                        }
                    }
                }
                // next iteration's local argmax, adjacent to the updates so the
                // SEL/FMNMX tree interleaves with in-flight loads
                #pragma unroll
                for (int c = 0; c < 2; c++)
                    LOCAL_ARGMAX(h[c], mask[c], labs[c], lj[c], lsgn[c]);
            }
        }

        // ---- outputs for both chains ----
        #pragma unroll
        for (int c = 0; c < 2; c++) {
            const int sl = wid * 4 + 2 * sp + c;
            const int s  = tile + sl;
            #pragma unroll
            for (int i = 0; i < 5; i++)
                if (lane == i) out_coef[(size_t)idxs[c][i] * 65536 + s] = xs[c][i];

            float r0 = 0.f, r1 = 0.f;
            #pragma unroll
            for (int i = 0; i < 5; i++) {
                const float* dr = &g_dnormT[idxs[c][i]][0];
                r0 += xs[c][i] * dr[lane];
                r1 += xs[c][i] * dr[lane + 32];
            }
            sh_z[lane * 33 + sl]        = r0;
            sh_z[(lane + 32) * 33 + sl] = r1;
        }
    }
    __syncthreads();

    // ---- Phase 3: coalesced z_dl_st write + loss reduce (fp32 partials) ----
    float partf = 0.f;
    float* oz = out_z + (size_t)b * 65536 + hw0;
    for (int i = tid; i < 2048; i += 256) {
        int m = i >> 5, sl = i & 31;
        float xv = sh_x[m * 32 + sl];
        float r  = sh_z[m * 33 + sl];
        float dd = r - xv;
        partf += dd * dd;
        oz[m * 1024 + sl] = xv + dd;   // z_e + (z_dl - z_e)
    }
    sh_red[tid] = (double)partf;
    __syncthreads();
    for (int sft = 128; sft; sft >>= 1) {
        if (tid < sft) sh_red[tid] += sh_red[tid + sft];
        __syncthreads();
    }

    // ---- fused final loss: last block reduces g_partial deterministically --
    if (tid == 0) {
        g_partial[blockIdx.x] = sh_red[0];
        __threadfence();
        unsigned ticket = atomicAdd(&g_done, 1u);
        sh_last = (ticket == NBLK - 1);
    }
    __syncthreads();
    if (sh_last) {
        double p = 0.0;
        for (int i = tid; i < NBLK; i += 256) p += g_partial[i];
        sh_red[tid] = p;
        __syncthreads();
        for (int sft = 128; sft; sft >>= 1) {
            if (tid < sft) sh_red[tid] += sh_red[tid + sft];
            __syncthreads();
        }
        if (tid == 0) {
            out_loss[0] = (float)(1.25 * sh_red[0] / 4194304.0);
            atomicExch(&g_done, 0u);   // reset for next graph replay
        }
    }
}

// ---------------- launch ------------------------------------------------------
extern "C" void kernel_launch(void* const* d_in, const int* in_sizes, int n_in,
                              void* d_out, int out_size) {
    const float* ze   = (const float*)d_in[0];
    const float* dict = (const float*)d_in[1];
    float* out      = (float*)d_out;
    float* out_z    = out;                 // 4,194,304
    float* out_loss = out + 4194304;       // 1
    float* out_coef = out + 4194305;       // 33,554,432

    cudaFuncSetAttribute(k_main, cudaFuncAttributeMaxDynamicSharedMemorySize,
                         SMEM_BYTES);

    k_gramraw<<<NAT, 128>>>(dict);
    k_prep<<<1152, 256>>>(dict);
    k_main<<<NBLK, 256, SMEM_BYTES>>>(ze, out_z, out_coef, out_loss);
}

// round 10
// speedup vs baseline: 1.1076x; 1.0294x over previous
#include <cuda_runtime.h>
#include <math.h>

#define NSIG 65536
#define NAT  512
#define MDIM 64
#define NBLK 2048            // NSIG / 32 signals per block
#define SMEM_FLOATS (2048 + 16384 + 2112)
#define SMEM_BYTES  (SMEM_FLOATS * 4)

// ---------------- device globals (scratch; no allocations allowed) ----------
__device__ __align__(16) float  g_dnormJ[MDIM][NAT];   // [m][j]
__device__ __align__(16) float  g_dnormT[NAT][MDIM];   // [j][m]
__device__ __align__(16) float  g_G[NAT][NAT];         // Gram (raw then scaled)
__device__ float  g_rn[NAT];
__device__ double g_partial[NBLK];
__device__ unsigned g_done = 0;

// ---------------- f32x2 packed-FMA helpers (Blackwell) ----------------------
__device__ __forceinline__ unsigned long long fma2(unsigned long long a,
                                                   unsigned long long b,
                                                   unsigned long long c) {
    unsigned long long r;
    asm("fma.rn.f32x2 %0, %1, %2, %3;" : "=l"(r) : "l"(a), "l"(b), "l"(c));
    return r;
}
__device__ __forceinline__ unsigned long long pack2(float x) {
    unsigned long long r;
    asm("mov.b64 %0, {%1, %1};" : "=l"(r) : "f"(x));
    return r;
}
__device__ __forceinline__ unsigned long long pk2(float a, float b) {
    unsigned long long r;
    asm("mov.b64 %0, {%1, %2};" : "=l"(r) : "f"(a), "f"(b));
    return r;
}
__device__ __forceinline__ float2 unpack2(unsigned long long v) {
    float2 f;
    asm("mov.b64 {%0, %1}, %2;" : "=f"(f.x), "=f"(f.y) : "l"(v));
    return f;
}

// ---------------- KA: raw Gram Ghat = D^T D (+ fused rn), MLP-8 -------------
__global__ void k_gramraw(const float* __restrict__ dict) {
    __shared__ float di[MDIM];
    const int i = blockIdx.x, tid = threadIdx.x;
    if (tid < MDIM) di[tid] = __ldg(dict + tid * NAT + i);
    __syncthreads();
    const int j0 = tid, j1 = tid + 256;
    float a0 = 0.f, a1 = 0.f, a2 = 0.f, a3 = 0.f;   // j0 chains
    float b0 = 0.f, b1 = 0.f, b2 = 0.f, b3 = 0.f;   // j1 chains
    #pragma unroll
    for (int m = 0; m < MDIM; m += 4) {
        float u0 = __ldg(dict + (m + 0) * NAT + j0);
        float u1 = __ldg(dict + (m + 1) * NAT + j0);
        float u2 = __ldg(dict + (m + 2) * NAT + j0);
        float u3 = __ldg(dict + (m + 3) * NAT + j0);
        float w0 = __ldg(dict + (m + 0) * NAT + j1);
        float w1 = __ldg(dict + (m + 1) * NAT + j1);
        float w2 = __ldg(dict + (m + 2) * NAT + j1);
        float w3 = __ldg(dict + (m + 3) * NAT + j1);
        a0 += di[m + 0] * u0; a1 += di[m + 1] * u1;
        a2 += di[m + 2] * u2; a3 += di[m + 3] * u3;
        b0 += di[m + 0] * w0; b1 += di[m + 1] * w1;
        b2 += di[m + 2] * w2; b3 += di[m + 3] * w3;
    }
    float v0 = (a0 + a1) + (a2 + a3);
    float v1 = (b0 + b1) + (b2 + b3);
    g_G[i][j0] = v0;
    g_G[i][j1] = v1;
    if (j0 == i) g_rn[i] = 1.f / fmaxf(sqrtf(v0), 1e-10f);
    if (j1 == i) g_rn[i] = 1.f / fmaxf(sqrtf(v1), 1e-10f);
}

// ---------------- KC: fused dnorm + Gram scaling (one launch) ---------------
__global__ void k_prep(const float* __restrict__ dict) {
    int bid = blockIdx.x;
    if (bid < 128) {                               // normalized dictionary
        int idx = bid * 256 + threadIdx.x;         // 32768 total
        int m = idx >> 9, j = idx & 511;
        float d = __ldg(dict + idx) * g_rn[j];
        g_dnormJ[m][j] = d;
        g_dnormT[j][m] = d;
    } else {                                       // G = Ghat * rn_i * rn_j
        int idx = (bid - 128) * 256 + threadIdx.x; // 262144 total
        int i = idx >> 9, j = idx & 511;
        float* gl = &g_G[0][0];
        gl[idx] = gl[idx] * (g_rn[i] * g_rn[j]);
    }
}

// atom index owned by (lane, t):  j = 128*(t>>2) + 4*lane + (t&3)
// (ascending t <=> ascending j within a lane: tie-break by t == tie-break by j)
#define JMAP(lane, t) (128 * ((t) >> 2) + 4 * (lane) + ((t) & 3))
#define TRI(i, j) ((i) * ((i) - 1) / 2 + (j))    // lower-tri flat index, i > j

// local masked abs-argmax over 16 owned atoms kept as 8 f32x2 pairs
// (unpack2 of a u64 register pair is register aliasing -> free)
#define LOCAL_ARGMAX64(h8, mk, LABS, LJ, LSGN) do {                          \
    float v8[8]; int m8[8];                                                  \
    _Pragma("unroll")                                                        \
    for (int p = 0; p < 8; p++) {                                            \
        float2 f = unpack2((h8)[p]);                                         \
        unsigned hb0 = __float_as_uint(f.x);                                 \
        unsigned hb1 = __float_as_uint(f.y);                                 \
        float a0 = (((mk) >> (2*p)) & 1u) ? 0.f                              \
                 : __uint_as_float(hb0 & 0x7FFFFFFFu);                       \
        float a1 = (((mk) >> (2*p+1)) & 1u) ? 0.f                            \
                 : __uint_as_float(hb1 & 0x7FFFFFFFu);                       \
        bool r = a1 > a0;                                                    \
        v8[p] = r ? a1 : a0;                                                 \
        m8[p] = r ? (((2*p+1) << 1) | (int)(hb1 >> 31))                      \
                  : (((2*p)   << 1) | (int)(hb0 >> 31));                     \
    }                                                                        \
    float v4[4]; int m4[4];                                                  \
    _Pragma("unroll")                                                        \
    for (int p = 0; p < 4; p++) {                                            \
        bool r = v8[2*p+1] > v8[2*p];                                        \
        v4[p] = r ? v8[2*p+1] : v8[2*p];                                     \
        m4[p] = r ? m8[2*p+1] : m8[2*p];                                     \
    }                                                                        \
    float v2[2]; int m2[2];                                                  \
    _Pragma("unroll")                                                        \
    for (int p = 0; p < 2; p++) {                                            \
        bool r = v4[2*p+1] > v4[2*p];                                        \
        v2[p] = r ? v4[2*p+1] : v4[2*p];                                     \
        m2[p] = r ? m4[2*p+1] : m4[2*p];                                     \
    }                                                                        \
    bool r1 = v2[1] > v2[0];                                                 \
    float lv = r1 ? v2[1] : v2[0];                                           \
    int   lm = r1 ? m2[1] : m2[0];                                           \
    (LABS) = __float_as_uint(lv);                                            \
    (LJ)   = (unsigned)JMAP(lane, lm >> 1);                                  \
    (LSGN) = (unsigned)(lm & 1);                                             \
} while (0)

// ---------------- K3: fused zero + GEMM + dual-chain OMP + outputs + loss ---
__global__ void __launch_bounds__(256, 2)
k_main(const float* __restrict__ ze, float* __restrict__ out_z,
       float* __restrict__ out_coef, float* __restrict__ out_loss) {
    extern __shared__ float smem[];
    float* sh_x = smem;                                       // [64][32]  2048
    unsigned long long* sh_h64 =
        (unsigned long long*)(smem + 2048);                   // [32][256] u64
    float* sh_z = smem + 2048 + 16384;                        // [64][33]  2112
    __shared__ double sh_red[256];
    __shared__ int sh_last;

    const int tid  = threadIdx.x;
    const int lane = tid & 31;
    const int wid  = tid >> 5;
    const int tile = blockIdx.x * 32;
    const int b    = tile >> 10;
    const int hw0  = tile & 1023;
    const float* zb = ze + (size_t)b * 65536 + hw0;

    // ---- zero this block's 32 coeff columns (hides under GEMM) ----
    {
        float* cz = out_coef + tile;
        for (int i = tid; i < NAT * 32; i += 256) {
            int j = i >> 5, sl = i & 31;
            cz[(size_t)j * 65536 + sl] = 0.f;
        }
    }

    // ---- load X tile: sh_x[m][sl] (coalesced) ----
    for (int i = tid; i < 2048; i += 256) {
        int m = i >> 5, sl = i & 31;
        sh_x[i] = zb[m * 1024 + sl];
    }
    __syncthreads();

    // ---- Phase 1: single-pass GEMM, 4 signals; stage packed pairs ----
    {
        unsigned long long acc[4][8];
        #pragma unroll
        for (int c = 0; c < 4; c++)
            #pragma unroll
            for (int p = 0; p < 8; p++) acc[c][p] = 0ull;

        for (int m = 0; m < MDIM; m++) {
            const ulonglong2* drow = (const ulonglong2*)(&g_dnormJ[m][0]);
            ulonglong2 d0 = drow[lane];
            ulonglong2 d1 = drow[32 + lane];
            ulonglong2 d2 = drow[64 + lane];
            ulonglong2 d3 = drow[96 + lane];
            unsigned long long dv[8] = {d0.x, d0.y, d1.x, d1.y,
                                        d2.x, d2.y, d3.x, d3.y};
            float4 xs4 = *(const float4*)(sh_x + m * 32 + wid * 4);
            float xc[4] = {xs4.x, xs4.y, xs4.z, xs4.w};
            #pragma unroll
            for (int c = 0; c < 4; c++) {
                unsigned long long xp = pack2(xc[c]);
                #pragma unroll
                for (int p = 0; p < 8; p++)
                    acc[c][p] = fma2(dv[p], xp, acc[c][p]);
            }
        }
        #pragma unroll
        for (int c = 0; c < 4; c++)
            #pragma unroll
            for (int p = 0; p < 8; p++)
                sh_h64[(c * 8 + p) * 256 + tid] = acc[c][p];
    }
    // thread-private staging: no __syncthreads needed

    // ---- Phase 2: OMP, TWO interleaved chains per warp per pass ----
    #pragma unroll 1
    for (int sp = 0; sp < 2; ++sp) {
        // chains c=0,1 -> signals sl = wid*4 + 2*sp + c
        unsigned long long h2[2][8];
        #pragma unroll
        for (int c = 0; c < 2; c++)
            #pragma unroll
            for (int p = 0; p < 8; p++)
                h2[c][p] = sh_h64[((2 * sp + c) * 8 + p) * 256 + tid];

        unsigned mask[2] = {0u, 0u};
        int   idxs[2][5];
        float xs[2][5], y[2][5], rv[2][5], Lm[2][10];
        unsigned labs[2], lj[2], lsgn[2];

        // initial local argmax (fused into the update loop for k>=1)
        #pragma unroll
        for (int c = 0; c < 2; c++)
            LOCAL_ARGMAX64(h2[c], mask[c], labs[c], lj[c], lsgn[c]);

        #pragma unroll
        for (int k = 0; k < 5; k++) {
            // ---- cross-lane argmax: redux pairs back-to-back (overlap) ----
            unsigned wmax[2], kmin[2];
            #pragma unroll
            for (int c = 0; c < 2; c++)
                wmax[c] = __reduce_max_sync(0xffffffffu, labs[c]);
            #pragma unroll
            for (int c = 0; c < 2; c++) {
                unsigned cand = (labs[c] == wmax[c])
                              ? ((lj[c] << 1) | lsgn[c]) : 0xFFFFFFFFu;
                kmin[c] = __reduce_min_sync(0xffffffffu, cand);
            }

            int bestj[2]; float h_sel[2];
            #pragma unroll
            for (int c = 0; c < 2; c++) {
                bestj[c] = (int)(kmin[c] >> 1);
                float av = __uint_as_float(wmax[c]);
                h_sel[c] = (kmin[c] & 1u) ? -av : av;
                if (((bestj[c] >> 2) & 31) == lane) {
                    int tb = (((bestj[c] >> 7) << 2) | (bestj[c] & 3));
                    mask[c] |= 1u << tb;
                }
                idxs[c][k] = bestj[c];
            }

            // ---- G_stack scalars for Cholesky (both chains issued together) --
            float gs[2][4];
            #pragma unroll
            for (int c = 0; c < 2; c++)
                #pragma unroll
                for (int i = 0; i < 4; i++) if (i < k)
                    gs[c][i] = __ldg(&g_G[bestj[c]][idxs[c][i]]);

            #pragma unroll
            for (int c = 0; c < 2; c++) {
                // ---- incremental Cholesky ----
                if (k == 0) {
                    rv[c][0] = 1.f;
                } else {
                    float w[4]; float s2 = 0.f;
                    #pragma unroll
                    for (int i = 0; i < 4; i++) if (i < k) {
                        float v = gs[c][i];
                        #pragma unroll
                        for (int j2 = 0; j2 < 4; j2++)
                            if (j2 < i) v -= Lm[c][TRI(i, j2)] * w[j2];
                        w[i] = (i == 0) ? v : v * rv[c][i];
                        Lm[c][TRI(k, i)] = w[i];
                        s2 += w[i] * w[i];
                    }
                    rv[c][k] = __frcp_rn(sqrtf(1.f - s2));
                }

                // ---- forward solve collapses exactly:  y_k = h_sel * rinv_k
                y[c][k] = (k == 0) ? h_sel[c] : h_sel[c] * rv[c][k];
            }

            // ---- backward solves with in-place dx (both chains) ----
            float dx[2][5];
            #pragma unroll
            for (int c = 0; c < 2; c++) {
                #pragma unroll
                for (int i = 4; i >= 0; i--) if (i <= k) {
                    float v = y[c][i];
                    #pragma unroll
                    for (int j2 = 0; j2 < 5; j2++)
                        if (j2 > i && j2 <= k) v -= Lm[c][TRI(j2, i)] * xs[c][j2];
                    float xn = (i == 0) ? v : v * rv[c][i];
                    dx[c][i] = (i < k) ? (xn - xs[c][i]) : xn;
                    xs[c][i] = xn;
                }
            }

            // ---- fused: packed delta residual update + NEXT local argmax ----
            if (k < 4) {
                #pragma unroll
                for (int c = 0; c < 2; c++) {
                    #pragma unroll
                    for (int i = 0; i < 4; i++) if (i <= k) {
                        const float4* gri = (const float4*)(&g_G[idxs[c][i]][0]);
                        unsigned long long dxn = pack2(-dx[c][i]);
                        #pragma unroll
                        for (int q = 0; q < 4; q++) {
                            float4 g4 = __ldg(gri + 32 * q + lane);
                            h2[c][2*q]   = fma2(pk2(g4.x, g4.y), dxn, h2[c][2*q]);
                            h2[c][2*q+1] = fma2(pk2(g4.z, g4.w), dxn, h2[c][2*q+1]);
                        }
                    }
                }
                // next iteration's local argmax, adjacent to the updates so the
                // SEL/FMNMX tree interleaves with in-flight loads
                #pragma unroll
                for (int c = 0; c < 2; c++)
                    LOCAL_ARGMAX64(h2[c], mask[c], labs[c], lj[c], lsgn[c]);
            }
        }

        // ---- outputs for both chains ----
        #pragma unroll
        for (int c = 0; c < 2; c++) {
            const int sl = wid * 4 + 2 * sp + c;
            const int s  = tile + sl;
            #pragma unroll
            for (int i = 0; i < 5; i++)
                if (lane == i) out_coef[(size_t)idxs[c][i] * 65536 + s] = xs[c][i];

            float r0 = 0.f, r1 = 0.f;
            #pragma unroll
            for (int i = 0; i < 5; i++) {
                const float* dr = &g_dnormT[idxs[c][i]][0];
                r0 += xs[c][i] * dr[lane];
                r1 += xs[c][i] * dr[lane + 32];
            }
            sh_z[lane * 33 + sl]        = r0;
            sh_z[(lane + 32) * 33 + sl] = r1;
        }
    }
    __syncthreads();

    // ---- Phase 3: coalesced z_dl_st write + loss reduce (fp32 partials) ----
    float partf = 0.f;
    float* oz = out_z + (size_t)b * 65536 + hw0;
    for (int i = tid; i < 2048; i += 256) {
        int m = i >> 5, sl = i & 31;
        float xv = sh_x[m * 32 + sl];
        float r  = sh_z[m * 33 + sl];
        float dd = r - xv;
        partf += dd * dd;
        oz[m * 1024 + sl] = xv + dd;   // z_e + (z_dl - z_e)
    }
    sh_red[tid] = (double)partf;
    __syncthreads();
    for (int sft = 128; sft; sft >>= 1) {
        if (tid < sft) sh_red[tid] += sh_red[tid + sft];
        __syncthreads();
    }

    // ---- fused final loss: last block reduces g_partial deterministically --
    if (tid == 0) {
        g_partial[blockIdx.x] = sh_red[0];
        __threadfence();
        unsigned ticket = atomicAdd(&g_done, 1u);
        sh_last = (ticket == NBLK - 1);
    }
    __syncthreads();
    if (sh_last) {
        double p = 0.0;
        for (int i = tid; i < NBLK; i += 256) p += g_partial[i];
        sh_red[tid] = p;
        __syncthreads();
        for (int sft = 128; sft; sft >>= 1) {
            if (tid < sft) sh_red[tid] += sh_red[tid + sft];
            __syncthreads();
        }
        if (tid == 0) {
            out_loss[0] = (float)(1.25 * sh_red[0] / 4194304.0);
            atomicExch(&g_done, 0u);   // reset for next graph replay
        }
    }
}

// ---------------- launch ------------------------------------------------------
extern "C" void kernel_launch(void* const* d_in, const int* in_sizes, int n_in,
                              void* d_out, int out_size) {
    const float* ze   = (const float*)d_in[0];
    const float* dict = (const float*)d_in[1];
    float* out      = (float*)d_out;
    float* out_z    = out;                 // 4,194,304
    float* out_loss = out + 4194304;       // 1
    float* out_coef = out + 4194305;       // 33,554,432

    cudaFuncSetAttribute(k_main, cudaFuncAttributeMaxDynamicSharedMemorySize,
                         SMEM_BYTES);

    k_gramraw<<<NAT, 256>>>(dict);
    k_prep<<<1152, 256>>>(dict);
    k_main<<<NBLK, 256, SMEM_BYTES>>>(ze, out_z, out_coef, out_loss);
}

// round 11
// speedup vs baseline: 1.1735x; 1.0595x over previous
#include <cuda_runtime.h>
#include <math.h>

#define NSIG 65536
#define NAT  512
#define MDIM 64
#define NBLK 2048            // NSIG / 32 signals per block
#define SMEM_FLOATS (2048 + 16384 + 2112)
#define SMEM_BYTES  (SMEM_FLOATS * 4)

// ---------------- device globals (scratch; no allocations allowed) ----------
__device__ __align__(16) float  g_dnormJ[MDIM][NAT];   // [m][j]
__device__ __align__(16) float  g_dnormT[NAT][MDIM];   // [j][m]
__device__ __align__(16) float  g_G[NAT][NAT];         // Gram (raw then scaled)
__device__ float  g_rn[NAT];
__device__ double g_partial[NBLK];
__device__ unsigned g_done = 0;

// ---------------- f32x2 packed-FMA helpers (Blackwell) ----------------------
__device__ __forceinline__ unsigned long long fma2(unsigned long long a,
                                                   unsigned long long b,
                                                   unsigned long long c) {
    unsigned long long r;
    asm("fma.rn.f32x2 %0, %1, %2, %3;" : "=l"(r) : "l"(a), "l"(b), "l"(c));
    return r;
}
__device__ __forceinline__ unsigned long long pack2(float x) {
    unsigned long long r;
    asm("mov.b64 %0, {%1, %1};" : "=l"(r) : "f"(x));
    return r;
}
__device__ __forceinline__ unsigned long long pk2(float a, float b) {
    unsigned long long r;
    asm("mov.b64 %0, {%1, %2};" : "=l"(r) : "f"(a), "f"(b));
    return r;
}
__device__ __forceinline__ float2 unpack2(unsigned long long v) {
    float2 f;
    asm("mov.b64 {%0, %1}, %2;" : "=f"(f.x), "=f"(f.y) : "l"(v));
    return f;
}

// ---------------- KA: raw Gram Ghat = D^T D (+ fused rn), MLP-8 -------------
__global__ void k_gramraw(const float* __restrict__ dict) {
    __shared__ float di[MDIM];
    const int i = blockIdx.x, tid = threadIdx.x;
    if (tid < MDIM) di[tid] = __ldg(dict + tid * NAT + i);
    __syncthreads();
    const int j0 = tid, j1 = tid + 256;
    float a0 = 0.f, a1 = 0.f, a2 = 0.f, a3 = 0.f;   // j0 chains
    float b0 = 0.f, b1 = 0.f, b2 = 0.f, b3 = 0.f;   // j1 chains
    #pragma unroll
    for (int m = 0; m < MDIM; m += 4) {
        float u0 = __ldg(dict + (m + 0) * NAT + j0);
        float u1 = __ldg(dict + (m + 1) * NAT + j0);
        float u2 = __ldg(dict + (m + 2) * NAT + j0);
        float u3 = __ldg(dict + (m + 3) * NAT + j0);
        float w0 = __ldg(dict + (m + 0) * NAT + j1);
        float w1 = __ldg(dict + (m + 1) * NAT + j1);
        float w2 = __ldg(dict + (m + 2) * NAT + j1);
        float w3 = __ldg(dict + (m + 3) * NAT + j1);
        a0 += di[m + 0] * u0; a1 += di[m + 1] * u1;
        a2 += di[m + 2] * u2; a3 += di[m + 3] * u3;
        b0 += di[m + 0] * w0; b1 += di[m + 1] * w1;
        b2 += di[m + 2] * w2; b3 += di[m + 3] * w3;
    }
    float v0 = (a0 + a1) + (a2 + a3);
    float v1 = (b0 + b1) + (b2 + b3);
    g_G[i][j0] = v0;
    g_G[i][j1] = v1;
    if (j0 == i) g_rn[i] = 1.f / fmaxf(sqrtf(v0), 1e-10f);
    if (j1 == i) g_rn[i] = 1.f / fmaxf(sqrtf(v1), 1e-10f);
}

// ---------------- KC: fused dnorm + Gram scaling (one launch) ---------------
__global__ void k_prep(const float* __restrict__ dict) {
    int bid = blockIdx.x;
    if (bid < 128) {                               // normalized dictionary
        int idx = bid * 256 + threadIdx.x;         // 32768 total
        int m = idx >> 9, j = idx & 511;
        float d = __ldg(dict + idx) * g_rn[j];
        g_dnormJ[m][j] = d;
        g_dnormT[j][m] = d;
    } else {                                       // G = Ghat * rn_i * rn_j
        int idx = (bid - 128) * 256 + threadIdx.x; // 262144 total
        int i = idx >> 9, j = idx & 511;
        float* gl = &g_G[0][0];
        gl[idx] = gl[idx] * (g_rn[i] * g_rn[j]);
    }
}

// atom index owned by (lane, t):  j = 128*(t>>2) + 4*lane + (t&3)
// (ascending t <=> ascending j within a lane: tie-break by t == tie-break by j)
#define JMAP(lane, t) (128 * ((t) >> 2) + 4 * (lane) + ((t) & 3))
#define TRI(i, j) ((i) * ((i) - 1) / 2 + (j))    // lower-tri flat index, i > j

// local masked abs-argmax over 16 owned atoms kept as 8 f32x2 pairs
// (unpack2 of a u64 register pair is register aliasing -> free)
#define LOCAL_ARGMAX64(h8, mk, LABS, LJ, LSGN) do {                          \
    float v8[8]; int m8[8];                                                  \
    _Pragma("unroll")                                                        \
    for (int p = 0; p < 8; p++) {                                            \
        float2 f = unpack2((h8)[p]);                                         \
        unsigned hb0 = __float_as_uint(f.x);                                 \
        unsigned hb1 = __float_as_uint(f.y);                                 \
        float a0 = (((mk) >> (2*p)) & 1u) ? 0.f                              \
                 : __uint_as_float(hb0 & 0x7FFFFFFFu);                       \
        float a1 = (((mk) >> (2*p+1)) & 1u) ? 0.f                            \
                 : __uint_as_float(hb1 & 0x7FFFFFFFu);                       \
        bool r = a1 > a0;                                                    \
        v8[p] = r ? a1 : a0;                                                 \
        m8[p] = r ? (((2*p+1) << 1) | (int)(hb1 >> 31))                      \
                  : (((2*p)   << 1) | (int)(hb0 >> 31));                     \
    }                                                                        \
    float v4[4]; int m4[4];                                                  \
    _Pragma("unroll")                                                        \
    for (int p = 0; p < 4; p++) {                                            \
        bool r = v8[2*p+1] > v8[2*p];                                        \
        v4[p] = r ? v8[2*p+1] : v8[2*p];                                     \
        m4[p] = r ? m8[2*p+1] : m8[2*p];                                     \
    }                                                                        \
    float v2[2]; int m2[2];                                                  \
    _Pragma("unroll")                                                        \
    for (int p = 0; p < 2; p++) {                                            \
        bool r = v4[2*p+1] > v4[2*p];                                        \
        v2[p] = r ? v4[2*p+1] : v4[2*p];                                     \
        m2[p] = r ? m4[2*p+1] : m4[2*p];                                     \
    }                                                                        \
    bool r1 = v2[1] > v2[0];                                                 \
    float lv = r1 ? v2[1] : v2[0];                                           \
    int   lm = r1 ? m2[1] : m2[0];                                           \
    (LABS) = __float_as_uint(lv);                                            \
    (LJ)   = (unsigned)JMAP(lane, lm >> 1);                                  \
    (LSGN) = (unsigned)(lm & 1);                                             \
} while (0)

// ---------------- K3: fused zero + GEMM + dual-chain OMP + outputs + loss ---
__global__ void __launch_bounds__(256, 2)
k_main(const float* __restrict__ ze, float* __restrict__ out_z,
       float* __restrict__ out_coef, float* __restrict__ out_loss) {
    extern __shared__ float smem[];
    float* sh_x = smem;                                       // [64][32]  2048
    unsigned long long* sh_h64 =
        (unsigned long long*)(smem + 2048);                   // [32][256] u64
    float* sh_z = smem + 2048 + 16384;                        // [64][33]  2112
    __shared__ double sh_red[256];
    __shared__ int sh_last;

    const int tid  = threadIdx.x;
    const int lane = tid & 31;
    const int wid  = tid >> 5;
    const int tile = blockIdx.x * 32;
    const int b    = tile >> 10;
    const int hw0  = tile & 1023;
    const float* zb = ze + (size_t)b * 65536 + hw0;

    // ---- zero this block's 32 coeff columns (hides under GEMM) ----
    {
        float* cz = out_coef + tile;
        for (int i = tid; i < NAT * 32; i += 256) {
            int j = i >> 5, sl = i & 31;
            cz[(size_t)j * 65536 + sl] = 0.f;
        }
    }

    // ---- load X tile: sh_x[m][sl] (coalesced) ----
    for (int i = tid; i < 2048; i += 256) {
        int m = i >> 5, sl = i & 31;
        sh_x[i] = zb[m * 1024 + sl];
    }
    __syncthreads();

    // ---- Phase 1: warp-pair GEMM — 8 signals x 8 atoms per thread ----
    // warp-pair p2 = wid>>1 owns signals p2*8 .. p2*8+7;
    // parity ph = wid&1 owns atom quadrants 2ph, 2ph+1 (t = ph*8 .. ph*8+7).
    // Dict bytes per fma2 halved vs 4-signal layout (2 LDG.128 per m for 32 fma2).
    {
        const int p2 = wid >> 1;
        const int ph = wid & 1;
        unsigned long long acc[8][4];
        #pragma unroll
        for (int s = 0; s < 8; s++)
            #pragma unroll
            for (int p = 0; p < 4; p++) acc[s][p] = 0ull;

        for (int m = 0; m < MDIM; m++) {
            const ulonglong2* drow = (const ulonglong2*)(&g_dnormJ[m][0]);
            ulonglong2 da = drow[64 * ph + lane];        // quadrant 2ph
            ulonglong2 db = drow[64 * ph + 32 + lane];   // quadrant 2ph+1
            unsigned long long dv[4] = {da.x, da.y, db.x, db.y};
            float4 xa = *(const float4*)(sh_x + m * 32 + p2 * 8);
            float4 xb = *(const float4*)(sh_x + m * 32 + p2 * 8 + 4);
            float xc[8] = {xa.x, xa.y, xa.z, xa.w, xb.x, xb.y, xb.z, xb.w};
            #pragma unroll
            for (int s = 0; s < 8; s++) {
                unsigned long long xp = pack2(xc[s]);
                #pragma unroll
                for (int p = 0; p < 4; p++)
                    acc[s][p] = fma2(dv[p], xp, acc[s][p]);
            }
        }
        // stage to the consumer-warp layout:
        // consumer (signal sl, slot p, tid_c = (sl>>2)*32 + lane) expects
        // pair p of 8; our pairs are slots ph*4 + p'.
        #pragma unroll
        for (int s = 0; s < 8; s++) {
            const int sl = p2 * 8 + s;
            #pragma unroll
            for (int p = 0; p < 4; p++)
                sh_h64[(((sl & 3) * 8) + ph * 4 + p) * 256 +
                       ((sl >> 2) * 32 + lane)] = acc[s][p];
        }
    }
    __syncthreads();   // cross-warp staging

    // ---- Phase 2: OMP, TWO interleaved chains per warp per pass ----
    #pragma unroll 1
    for (int sp = 0; sp < 2; ++sp) {
        // chains c=0,1 -> signals sl = wid*4 + 2*sp + c
        unsigned long long h2[2][8];
        #pragma unroll
        for (int c = 0; c < 2; c++)
            #pragma unroll
            for (int p = 0; p < 8; p++)
                h2[c][p] = sh_h64[((2 * sp + c) * 8 + p) * 256 + tid];

        unsigned mask[2] = {0u, 0u};
        int   idxs[2][5];
        float xs[2][5], y[2][5], rv[2][5], Lm[2][10];
        unsigned labs[2], lj[2], lsgn[2];

        // initial local argmax (fused into the update loop for k>=1)
        #pragma unroll
        for (int c = 0; c < 2; c++)
            LOCAL_ARGMAX64(h2[c], mask[c], labs[c], lj[c], lsgn[c]);

        #pragma unroll
        for (int k = 0; k < 5; k++) {
            // ---- cross-lane argmax: redux pairs back-to-back (overlap) ----
            unsigned wmax[2], kmin[2];
            #pragma unroll
            for (int c = 0; c < 2; c++)
                wmax[c] = __reduce_max_sync(0xffffffffu, labs[c]);
            #pragma unroll
            for (int c = 0; c < 2; c++) {
                unsigned cand = (labs[c] == wmax[c])
                              ? ((lj[c] << 1) | lsgn[c]) : 0xFFFFFFFFu;
                kmin[c] = __reduce_min_sync(0xffffffffu, cand);
            }

            int bestj[2]; float h_sel[2];
            #pragma unroll
            for (int c = 0; c < 2; c++) {
                bestj[c] = (int)(kmin[c] >> 1);
                float av = __uint_as_float(wmax[c]);
                h_sel[c] = (kmin[c] & 1u) ? -av : av;
                if (((bestj[c] >> 2) & 31) == lane) {
                    int tb = (((bestj[c] >> 7) << 2) | (bestj[c] & 3));
                    mask[c] |= 1u << tb;
                }
                idxs[c][k] = bestj[c];
            }

            // ---- G_stack scalars for Cholesky (both chains issued together) --
            float gs[2][4];
            #pragma unroll
            for (int c = 0; c < 2; c++)
                #pragma unroll
                for (int i = 0; i < 4; i++) if (i < k)
                    gs[c][i] = __ldg(&g_G[bestj[c]][idxs[c][i]]);

            #pragma unroll
            for (int c = 0; c < 2; c++) {
                // ---- incremental Cholesky ----
                if (k == 0) {
                    rv[c][0] = 1.f;
                } else {
                    float w[4]; float s2 = 0.f;
                    #pragma unroll
                    for (int i = 0; i < 4; i++) if (i < k) {
                        float v = gs[c][i];
                        #pragma unroll
                        for (int j2 = 0; j2 < 4; j2++)
                            if (j2 < i) v -= Lm[c][TRI(i, j2)] * w[j2];
                        w[i] = (i == 0) ? v : v * rv[c][i];
                        Lm[c][TRI(k, i)] = w[i];
                        s2 += w[i] * w[i];
                    }
                    rv[c][k] = __frcp_rn(sqrtf(1.f - s2));
                }

                // ---- forward solve collapses exactly:  y_k = h_sel * rinv_k
                y[c][k] = (k == 0) ? h_sel[c] : h_sel[c] * rv[c][k];
            }

            // ---- backward solves with in-place dx (both chains) ----
            float dx[2][5];
            #pragma unroll
            for (int c = 0; c < 2; c++) {
                #pragma unroll
                for (int i = 4; i >= 0; i--) if (i <= k) {
                    float v = y[c][i];
                    #pragma unroll
                    for (int j2 = 0; j2 < 5; j2++)
                        if (j2 > i && j2 <= k) v -= Lm[c][TRI(j2, i)] * xs[c][j2];
                    float xn = (i == 0) ? v : v * rv[c][i];
                    dx[c][i] = (i < k) ? (xn - xs[c][i]) : xn;
                    xs[c][i] = xn;
                }
            }

            // ---- fused: packed delta residual update + NEXT local argmax ----
            if (k < 4) {
                #pragma unroll
                for (int c = 0; c < 2; c++) {
                    #pragma unroll
                    for (int i = 0; i < 4; i++) if (i <= k) {
                        const float4* gri = (const float4*)(&g_G[idxs[c][i]][0]);
                        unsigned long long dxn = pack2(-dx[c][i]);
                        #pragma unroll
                        for (int q = 0; q < 4; q++) {
                            float4 g4 = __ldg(gri + 32 * q + lane);
                            h2[c][2*q]   = fma2(pk2(g4.x, g4.y), dxn, h2[c][2*q]);
                            h2[c][2*q+1] = fma2(pk2(g4.z, g4.w), dxn, h2[c][2*q+1]);
                        }
                    }
                }
                // next iteration's local argmax, adjacent to the updates so the
                // SEL/FMNMX tree interleaves with in-flight loads
                #pragma unroll
                for (int c = 0; c < 2; c++)
                    LOCAL_ARGMAX64(h2[c], mask[c], labs[c], lj[c], lsgn[c]);
            }
        }

        // ---- outputs for both chains ----
        #pragma unroll
        for (int c = 0; c < 2; c++) {
            const int sl = wid * 4 + 2 * sp + c;
            const int s  = tile + sl;
            #pragma unroll
            for (int i = 0; i < 5; i++)
                if (lane == i) out_coef[(size_t)idxs[c][i] * 65536 + s] = xs[c][i];

            float r0 = 0.f, r1 = 0.f;
            #pragma unroll
            for (int i = 0; i < 5; i++) {
                const float* dr = &g_dnormT[idxs[c][i]][0];
                r0 += xs[c][i] * dr[lane];
                r1 += xs[c][i] * dr[lane + 32];
            }
            sh_z[lane * 33 + sl]        = r0;
            sh_z[(lane + 32) * 33 + sl] = r1;
        }
    }
    __syncthreads();

    // ---- Phase 3: coalesced z_dl_st write + loss reduce (fp32 partials) ----
    float partf = 0.f;
    float* oz = out_z + (size_t)b * 65536 + hw0;
    for (int i = tid; i < 2048; i += 256) {
        int m = i >> 5, sl = i & 31;
        float xv = sh_x[m * 32 + sl];
        float r  = sh_z[m * 33 + sl];
        float dd = r - xv;
        partf += dd * dd;
        oz[m * 1024 + sl] = xv + dd;   // z_e + (z_dl - z_e)
    }
    sh_red[tid] = (double)partf;
    __syncthreads();
    for (int sft = 128; sft; sft >>= 1) {
        if (tid < sft) sh_red[tid] += sh_red[tid + sft];
        __syncthreads();
    }

    // ---- fused final loss: last block reduces g_partial deterministically --
    if (tid == 0) {
        g_partial[blockIdx.x] = sh_red[0];
        __threadfence();
        unsigned ticket = atomicAdd(&g_done, 1u);
        sh_last = (ticket == NBLK - 1);
    }
    __syncthreads();
    if (sh_last) {
        double p = 0.0;
        for (int i = tid; i < NBLK; i += 256) p += g_partial[i];
        sh_red[tid] = p;
        __syncthreads();
        for (int sft = 128; sft; sft >>= 1) {
            if (tid < sft) sh_red[tid] += sh_red[tid + sft];
            __syncthreads();
        }
        if (tid == 0) {
            out_loss[0] = (float)(1.25 * sh_red[0] / 4194304.0);
            atomicExch(&g_done, 0u);   // reset for next graph replay
        }
    }
}

// ---------------- launch ------------------------------------------------------
extern "C" void kernel_launch(void* const* d_in, const int* in_sizes, int n_in,
                              void* d_out, int out_size) {
    const float* ze   = (const float*)d_in[0];
    const float* dict = (const float*)d_in[1];
    float* out      = (float*)d_out;
    float* out_z    = out;                 // 4,194,304
    float* out_loss = out + 4194304;       // 1
    float* out_coef = out + 4194305;       // 33,554,432

    cudaFuncSetAttribute(k_main, cudaFuncAttributeMaxDynamicSharedMemorySize,
                         SMEM_BYTES);

    k_gramraw<<<NAT, 256>>>(dict);
    k_prep<<<1152, 256>>>(dict);
    k_main<<<NBLK, 256, SMEM_BYTES>>>(ze, out_z, out_coef, out_loss);
}